// round 11
// baseline (speedup 1.0000x reference)
#include <cuda_runtime.h>

#define BB 4096
#define PB 2048   // f32x2 pairs per row (BB/2)

// padded spatial layouts: S1 16x16 (14x14 interior), S2/S3 9x9 (7x7 interior)
constexpr int S1R = 32 * 256;   // 8192 rows
constexpr int S2R = 64 * 81;    // 5184 rows
constexpr int S3R = 64 * 81;
constexpr int S4N = 256;

typedef unsigned long long ull;

// ---------------- packed f32x2 helpers ----------------
__device__ __forceinline__ ull fma2(ull a, ull b, ull c) {
    ull d; asm("fma.rn.f32x2 %0, %1, %2, %3;" : "=l"(d) : "l"(a), "l"(b), "l"(c)); return d;
}
__device__ __forceinline__ ull add2(ull a, ull b) {
    ull d; asm("add.rn.f32x2 %0, %1, %2;" : "=l"(d) : "l"(a), "l"(b)); return d;
}
__device__ __forceinline__ ull mul2(ull a, ull b) {
    ull d; asm("mul.rn.f32x2 %0, %1, %2;" : "=l"(d) : "l"(a), "l"(b)); return d;
}
__device__ __forceinline__ ull pk(float x) {
    ull d; unsigned u = __float_as_uint(x);
    asm("mov.b64 %0, {%1, %1};" : "=l"(d) : "r"(u)); return d;
}
__device__ __forceinline__ ull pku(unsigned u) {
    ull d; asm("mov.b64 %0, {%1, %1};" : "=l"(d) : "r"(u)); return d;
}
__device__ __forceinline__ void unpk(ull v, unsigned& lo, unsigned& hi) {
    asm("mov.b64 {%0, %1}, %2;" : "=r"(lo), "=r"(hi) : "l"(v));
}
__device__ __forceinline__ ull pack2(unsigned a, unsigned b) {
    ull d; asm("mov.b64 %0, {%1, %2};" : "=l"(d) : "r"(a), "r"(b)); return d;
}
__device__ __forceinline__ ulonglong2 ld2(const ull* p) {
    return *reinterpret_cast<const ulonglong2*>(p);
}
__device__ __forceinline__ void st2(ull* p, ulonglong2 v) {
    *reinterpret_cast<ulonglong2*>(p) = v;
}

// ---------------- scratch (device globals; allocation-free) ----------------
__device__ float g_S1[2][S1R * BB];     // padded [c][16x16][b]
__device__ float g_S2[2][S2R * BB];     // padded [c][9x9][b]
__device__ float g_S3[2][S3R * BB];
__device__ float g_S4[2][S4N * BB];
__device__ float g_D1[S1R * BB];        // conv1(x)+b1, padded like S1
__device__ float g_XT[784 * BB];        // x transposed [pixel][batch], unpadded
__device__ float g_w2a[64 * 9 * 32];    // [o][t][c]
__device__ float g_w2b[32 * 9 * 64];    // [c][t][o]
__device__ float g_w3a[64 * 9 * 64];    // [o][t][m]
__device__ float g_w3b[64 * 9 * 64];    // [m][t][o]
__device__ float g_w4t[3136 * 256];     // [k][j]
__device__ float g_w4r[49 * 256 * 64];  // [pos][j][c]

// ---------------- init / prep ----------------
__global__ void zero_state() {
    int stride = gridDim.x * blockDim.x;
    float4 z = make_float4(0.f, 0.f, 0.f, 0.f);
    const int n1 = S1R * BB / 4;
    const int n2 = S2R * BB / 4;
    const int n4 = S4N * BB / 4;
    for (int i = blockIdx.x * blockDim.x + threadIdx.x; i < n1; i += stride) {
        reinterpret_cast<float4*>(g_S1[0])[i] = z;
        reinterpret_cast<float4*>(g_S1[1])[i] = z;
        reinterpret_cast<float4*>(g_D1)[i] = z;
        if (i < n2) {
            reinterpret_cast<float4*>(g_S2[0])[i] = z;
            reinterpret_cast<float4*>(g_S2[1])[i] = z;
            reinterpret_cast<float4*>(g_S3[0])[i] = z;
            reinterpret_cast<float4*>(g_S3[1])[i] = z;
        }
        if (i < n4) reinterpret_cast<float4*>(g_S4[0])[i] = z;
    }
}

__global__ void transpose_x(const float* __restrict__ x) {
    __shared__ float tile[32][33];
    int p0 = blockIdx.x * 32, b0 = blockIdx.y * 32;
    int tx = threadIdx.x, ty = threadIdx.y;
    for (int i = ty; i < 32; i += 8) {
        int p = p0 + tx;
        tile[i][tx] = (p < 784) ? x[(b0 + i) * 784 + p] : 0.f;
    }
    __syncthreads();
    for (int i = ty; i < 32; i += 8) {
        int p = p0 + i;
        if (p < 784) g_XT[p * BB + b0 + tx] = tile[tx][i];
    }
}

__global__ void prep_weights(const float* __restrict__ w2,
                             const float* __restrict__ w3,
                             const float* __restrict__ w4) {
    int stride = gridDim.x * blockDim.x;
    for (int idx = blockIdx.x * blockDim.x + threadIdx.x; idx < 802816; idx += stride) {
        if (idx < 18432) {  // w2: [o=64][c=32][t=9]
            int o = idx / 288, r = idx % 288, c = r / 9, t = r % 9;
            float v = w2[idx];
            g_w2a[(o * 9 + t) * 32 + c] = v;
            g_w2b[(c * 9 + t) * 64 + o] = v;
        }
        if (idx < 36864) {  // w3: [m=64][o=64][t=9]
            int m = idx / 576, r = idx % 576, o = r / 9, t = r % 9;
            float v = w3[idx];
            g_w3a[(o * 9 + t) * 64 + m] = v;
            g_w3b[(m * 9 + t) * 64 + o] = v;
        }
        {   // w4: [j=256][k=3136]
            int j = idx / 3136, k = idx % 3136;
            float v = w4[idx];
            g_w4t[k * 256 + j] = v;
            int c = k / 49, pos = k % 49;
            g_w4r[(pos * 256 + j) * 64 + c] = v;
        }
    }
}

__global__ void compute_d1(const float* __restrict__ w1, const float* __restrict__ b1) {
    int b = blockIdx.x * 256 + threadIdx.x;
    int pos = blockIdx.y;
    int u = pos / 14, v = pos % 14;
    int c = blockIdx.z;
    float acc = b1[c];
#pragma unroll
    for (int di = 0; di < 3; di++) {
        int h = 2 * u + di - 1;
        if (h < 0 || h >= 28) continue;
#pragma unroll
        for (int dj = 0; dj < 3; dj++) {
            int w = 2 * v + dj - 1;
            if (w < 0 || w >= 28) continue;
            acc = fmaf(w1[c * 9 + di * 3 + dj], g_XT[(h * 28 + w) * BB + b], acc);
        }
    }
    g_D1[(c * 256 + (u + 1) * 16 + (v + 1)) * BB + b] = acc;
}

// ============================================================================
// Fused step: 16 output channels per block (halves L2 traffic vs 8),
// 4 samples/thread, sample-duplication packing (weights read as natural
// adjacent-channel ull pairs — no duplication).
// One 36.9 KB static smem buffer, two-phase staging in K2/K3.
// acc layout: acc{0..3}[8] = [sample][chan-pair].
// Role layout (grid.x = 3200):
//   [0,64): k4    [64,1632): k1    [1632,2416): k2    [2416,3200): k3
// ============================================================================
#define K4_BASE 0
#define K1_BASE 64
#define K2_BASE 1632
#define K3_BASE 2416
#define STEP_GRID 3200

// accumulate one tap: 4 duplicated samples x 8 weight pairs = 64 MACs
#define ACC_TAP(SV, WROW) do {                                                 \
    unsigned _a, _b, _c, _d;                                                   \
    unpk((SV).x, _a, _b); unpk((SV).y, _c, _d);                                \
    ull _d0 = pku(_a), _d1 = pku(_b), _d2 = pku(_c), _d3 = pku(_d);            \
    _Pragma("unroll")                                                          \
    for (int _p = 0; _p < 8; _p++) {                                           \
        ull _w = (WROW)[_p];                                                   \
        acc0[_p] = fma2(_d0, _w, acc0[_p]);                                    \
        acc1[_p] = fma2(_d1, _w, acc1[_p]);                                    \
        acc2[_p] = fma2(_d2, _w, acc2[_p]);                                    \
        acc3[_p] = fma2(_d3, _w, acc3[_p]);                                    \
    }                                                                          \
} while (0)

// copy 16 consecutive floats (64B aligned) global -> smem row
#define STAGE16(DSTROW, SRCP) do {                                             \
    const float4* _s = reinterpret_cast<const float4*>(SRCP);                  \
    float4* _d = reinterpret_cast<float4*>(&smw[(DSTROW) * 16]);               \
    _d[0] = _s[0]; _d[1] = _s[1]; _d[2] = _s[2]; _d[3] = _s[3];                \
} while (0)

__global__ void __launch_bounds__(256) step_kernel(int cur,
                                                   const float* __restrict__ b2,
                                                   const float* __restrict__ b3,
                                                   const float* __restrict__ b4) {
    __shared__ float smw[576 * 16];   // 36864 B
    ull* wsu = reinterpret_cast<ull*>(smw);
    const int tid = threadIdx.x;
    const int bx = blockIdx.x;
    const ull half = pk(0.5f);

    ull acc0[8], acc1[8], acc2[8], acc3[8];
#pragma unroll
    for (int p = 0; p < 8; p++) { acc0[p] = 0ull; acc1[p] = 0ull; acc2[p] = 0ull; acc3[p] = 0ull; }

    if (bx < K1_BASE) {
        // ---------------- K4: s4' = 0.5*(s4 + W4 s3 + b4) ----------------
        int idx = bx;
        const int bb = idx & 3;
        const int j0 = (idx >> 2) * 16;
        const int u = bb * 512 + 2 * tid;
        const ull* __restrict__ S3 = (const ull*)g_S3[cur];

        for (int ch = 0; ch < 8; ch++) {           // 8 chunks of 8 channels (392 k-rows)
            __syncthreads();
            for (int i = tid; i < 392; i += 256) STAGE16(i, &g_w4t[(ch * 392 + i) * 256 + j0]);
            __syncthreads();
            for (int cc = 0; cc < 8; cc++) {
                const ull* cb = S3 + ((ch * 8 + cc) * 81) * PB + u;
                const ull* wch = wsu + cc * 49 * 8;
                int kk = 0;
#pragma unroll
                for (int pp = 1; pp <= 7; pp++) {
#pragma unroll
                    for (int qq = 1; qq <= 7; qq++) {
                        ulonglong2 sv = ld2(cb + (pp * 9 + qq) * PB);
                        ACC_TAP(sv, wch + kk * 8); kk++;
                    }
                }
            }
        }

        const ull* __restrict__ S4i = (const ull*)g_S4[cur];
        ull* __restrict__ outp = (ull*)g_S4[cur ^ 1];
#pragma unroll
        for (int p = 0; p < 8; p++) {
            unsigned l0, h0, l1, h1, l2, h2, l3, h3;
            unpk(acc0[p], l0, h0); unpk(acc1[p], l1, h1);
            unpk(acc2[p], l2, h2); unpk(acc3[p], l3, h3);
#pragma unroll
            for (int hh = 0; hh < 2; hh++) {
                int chan = 2 * p + hh;
                ulonglong2 v;
                v.x = hh ? pack2(h0, h1) : pack2(l0, l1);
                v.y = hh ? pack2(h2, h3) : pack2(l2, l3);
                int ii = (j0 + chan) * PB + u;
                ull bias = pk(b4[j0 + chan]);
                ulonglong2 si = ld2(S4i + ii);
                ulonglong2 o;
                o.x = mul2(add2(add2(si.x, v.x), bias), half);
                o.y = mul2(add2(add2(si.y, v.y), bias), half);
                st2(outp + ii, o);
            }
        }
    } else if (bx < K2_BASE) {
        // ---------------- K1: s1' = 0.5*(s1 + d1 + tconv2(s2)) ----------------
        int idx = bx - K1_BASE;
        const int bb = idx & 3; idx >>= 2;
        const int pos = idx % 196;
        const int c0 = (idx / 196) * 16;
        const int u_ = bb * 512 + 2 * tid;

        for (int i = tid; i < 576; i += 256) STAGE16(i, &g_w2a[i * 32 + c0]);
        __syncthreads();

        const int uu = pos / 14, vv = pos % 14;
        // padded S2 row indices; structurally-absent taps -> halo row/col 8 (zeros)
        int p0r, p1r, wu0, wu1;
        if (uu & 1) { p0r = ((uu + 1) >> 1) + 1; wu0 = 0;
                      p1r = ((uu - 1) >> 1) + 1; wu1 = 2; }
        else        { p0r = (uu >> 1) + 1;       wu0 = 1;
                      p1r = 8;                   wu1 = 0; }
        int q0r, q1r, wv0, wv1;
        if (vv & 1) { q0r = ((vv + 1) >> 1) + 1; wv0 = 0;
                      q1r = ((vv - 1) >> 1) + 1; wv1 = 2; }
        else        { q0r = (vv >> 1) + 1;       wv0 = 1;
                      q1r = 8;                   wv1 = 0; }

        const int off00 = (p0r * 9 + q0r) * PB, wr00 = wu0 * 3 + wv0;
        const int off01 = (p0r * 9 + q1r) * PB, wr01 = wu0 * 3 + wv1;
        const int off10 = (p1r * 9 + q0r) * PB, wr10 = wu1 * 3 + wv0;
        const int off11 = (p1r * 9 + q1r) * PB, wr11 = wu1 * 3 + wv1;

        const ull* __restrict__ S2 = (const ull*)g_S2[cur];
#pragma unroll 2
        for (int o = 0; o < 64; o++) {
            const ull* base = S2 + o * 81 * PB + u_;
            const ull* wb = wsu + (o * 9) * 8;
            { ulonglong2 sv = ld2(base + off00); ACC_TAP(sv, wb + wr00 * 8); }
            { ulonglong2 sv = ld2(base + off01); ACC_TAP(sv, wb + wr01 * 8); }
            { ulonglong2 sv = ld2(base + off10); ACC_TAP(sv, wb + wr10 * 8); }
            { ulonglong2 sv = ld2(base + off11); ACC_TAP(sv, wb + wr11 * 8); }
        }

        const ull* __restrict__ S1i = (const ull*)g_S1[cur];
        const ull* __restrict__ D1 = (const ull*)g_D1;
        ull* __restrict__ S1o = (ull*)g_S1[cur ^ 1];
        const int obase = (uu + 1) * 16 + (vv + 1);
#pragma unroll
        for (int p = 0; p < 8; p++) {
            unsigned l0, h0, l1, h1, l2, h2, l3, h3;
            unpk(acc0[p], l0, h0); unpk(acc1[p], l1, h1);
            unpk(acc2[p], l2, h2); unpk(acc3[p], l3, h3);
#pragma unroll
            for (int hh = 0; hh < 2; hh++) {
                int chan = 2 * p + hh;
                ulonglong2 v;
                v.x = hh ? pack2(h0, h1) : pack2(l0, l1);
                v.y = hh ? pack2(h2, h3) : pack2(l2, l3);
                int ii = ((c0 + chan) * 256 + obase) * PB + u_;
                ulonglong2 si = ld2(S1i + ii), d1 = ld2(D1 + ii);
                ulonglong2 o;
                o.x = mul2(add2(add2(add2(si.x, d1.x), v.x), pk(0.f)), half);
                o.y = mul2(add2(add2(add2(si.y, d1.y), v.y), pk(0.f)), half);
                // note: +pk(0.f) adds exact zero — keeps op count symmetric; fp32 exact
                st2(S1o + ii, o);
            }
        }
    } else if (bx < K3_BASE) {
        // ---------------- K2: s2' = 0.5*(s2 + conv2(s1)+b2 + tconv3(s3)) ----------------
        int idx = bx - K2_BASE;
        const int bb = idx & 3; idx >>= 2;
        const int pos = idx % 49;
        const int o0 = (idx / 49) * 16;
        const int u_ = bb * 512 + 2 * tid;

        // phase A: conv2 slice (rows 0..287) + tconv3 m=0..31 (rows 288..575)
        for (int i = tid; i < 288; i += 256) STAGE16(i, &g_w2b[i * 64 + o0]);
        for (int i = tid; i < 288; i += 256) STAGE16(288 + i, &g_w3b[i * 64 + o0]);
        __syncthreads();

        const int p = pos / 7, q = pos % 7;

        // conv2(s1): stride 2, branchless (padded 16x16)
        {
            int off[9];
#pragma unroll
            for (int di = 0; di < 3; di++)
#pragma unroll
                for (int dj = 0; dj < 3; dj++)
                    off[di * 3 + dj] = ((2 * p + di) * 16 + (2 * q + dj)) * PB;
            const ull* __restrict__ S1 = (const ull*)g_S1[cur];
#pragma unroll 2
            for (int c = 0; c < 32; c++) {
                const ull* base = S1 + c * 256 * PB + u_;
                const ull* wb = wsu + (c * 9) * 8;
#pragma unroll
                for (int t = 0; t < 9; t++) {
                    ulonglong2 sv = ld2(base + off[t]);
                    ACC_TAP(sv, wb + t * 8);
                }
            }
        }
        // tconv3(s3): flipped taps, branchless (padded 9x9)
        {
            int off[9];
#pragma unroll
            for (int di = 0; di < 3; di++)
#pragma unroll
                for (int dj = 0; dj < 3; dj++)
                    off[di * 3 + dj] = ((p + 2 - di) * 9 + (q + 2 - dj)) * PB;
            const ull* __restrict__ S3 = (const ull*)g_S3[cur];
#pragma unroll 2
            for (int m = 0; m < 32; m++) {
                const ull* base = S3 + m * 81 * PB + u_;
                const ull* wb = wsu + ((288 + m * 9)) * 8;
#pragma unroll
                for (int t = 0; t < 9; t++) {
                    ulonglong2 sv = ld2(base + off[t]);
                    ACC_TAP(sv, wb + t * 8);
                }
            }
            // phase B: reload rows 0..287 with tconv3 m=32..63
            __syncthreads();
            for (int i = tid; i < 288; i += 256) STAGE16(i, &g_w3b[(288 + i) * 64 + o0]);
            __syncthreads();
#pragma unroll 2
            for (int m = 32; m < 64; m++) {
                const ull* base = S3 + m * 81 * PB + u_;
                const ull* wb = wsu + (((m - 32) * 9)) * 8;
#pragma unroll
                for (int t = 0; t < 9; t++) {
                    ulonglong2 sv = ld2(base + off[t]);
                    ACC_TAP(sv, wb + t * 8);
                }
            }
        }

        const ull* __restrict__ S2i = (const ull*)g_S2[cur];
        ull* __restrict__ outp = (ull*)g_S2[cur ^ 1];
        const int obase = (p + 1) * 9 + (q + 1);
#pragma unroll
        for (int pp2 = 0; pp2 < 8; pp2++) {
            unsigned l0, h0, l1, h1, l2, h2, l3, h3;
            unpk(acc0[pp2], l0, h0); unpk(acc1[pp2], l1, h1);
            unpk(acc2[pp2], l2, h2); unpk(acc3[pp2], l3, h3);
#pragma unroll
            for (int hh = 0; hh < 2; hh++) {
                int chan = 2 * pp2 + hh;
                ulonglong2 v;
                v.x = hh ? pack2(h0, h1) : pack2(l0, l1);
                v.y = hh ? pack2(h2, h3) : pack2(l2, l3);
                int ii = ((o0 + chan) * 81 + obase) * PB + u_;
                ull bias = pk(b2[o0 + chan]);
                ulonglong2 si = ld2(S2i + ii);
                ulonglong2 o;
                o.x = mul2(add2(add2(si.x, v.x), bias), half);
                o.y = mul2(add2(add2(si.y, v.y), bias), half);
                st2(outp + ii, o);
            }
        }
    } else {
        // ---------------- K3: s3' = 0.5*(s3 + conv3(s2)+b3 + W4^T s4) ----------------
        int idx = bx - K3_BASE;
        const int bb = idx & 3; idx >>= 2;
        const int pos = idx % 49;
        const int c0 = (idx / 49) * 16;
        const int u_ = bb * 512 + 2 * tid;

        for (int i = tid; i < 576; i += 256) STAGE16(i, &g_w3a[i * 64 + c0]);
        __syncthreads();

        const int p = pos / 7, q = pos % 7;

        // conv3(s2): stride 1, branchless (padded 9x9)
        {
            int off[9];
#pragma unroll
            for (int di = 0; di < 3; di++)
#pragma unroll
                for (int dj = 0; dj < 3; dj++)
                    off[di * 3 + dj] = ((p + di) * 9 + (q + dj)) * PB;
            const ull* __restrict__ S2 = (const ull*)g_S2[cur];
#pragma unroll 2
            for (int o = 0; o < 64; o++) {
                const ull* base = S2 + o * 81 * PB + u_;
                const ull* wb = wsu + (o * 9) * 8;
#pragma unroll
                for (int t = 0; t < 9; t++) {
                    ulonglong2 sv = ld2(base + off[t]);
                    ACC_TAP(sv, wb + t * 8);
                }
            }
        }
        // phase B: W4^T s4 (reload smem rows 0..255 with w4r[pos] slice)
        __syncthreads();
        for (int j = tid; j < 256; j += 256) STAGE16(j, &g_w4r[(pos * 256 + j) * 64 + c0]);
        __syncthreads();
        {
            const ull* __restrict__ S4 = (const ull*)g_S4[cur];
#pragma unroll 2
            for (int j = 0; j < 256; j++) {
                ulonglong2 sv = ld2(S4 + j * PB + u_);
                ACC_TAP(sv, wsu + j * 8);
            }
        }

        const ull* __restrict__ S3i = (const ull*)g_S3[cur];
        ull* __restrict__ outp = (ull*)g_S3[cur ^ 1];
        const int obase = (p + 1) * 9 + (q + 1);
#pragma unroll
        for (int pp2 = 0; pp2 < 8; pp2++) {
            unsigned l0, h0, l1, h1, l2, h2, l3, h3;
            unpk(acc0[pp2], l0, h0); unpk(acc1[pp2], l1, h1);
            unpk(acc2[pp2], l2, h2); unpk(acc3[pp2], l3, h3);
#pragma unroll
            for (int hh = 0; hh < 2; hh++) {
                int chan = 2 * pp2 + hh;
                ulonglong2 v;
                v.x = hh ? pack2(h0, h1) : pack2(l0, l1);
                v.y = hh ? pack2(h2, h3) : pack2(l2, l3);
                int ii = ((c0 + chan) * 81 + obase) * PB + u_;
                ull bias = pk(b3[c0 + chan]);
                ulonglong2 si = ld2(S3i + ii);
                ulonglong2 o;
                o.x = mul2(add2(add2(si.x, v.x), bias), half);
                o.y = mul2(add2(add2(si.y, v.y), bias), half);
                st2(outp + ii, o);
            }
        }
    }
}

// ============================================================================
// Forward-only kernels for energy readout (run once) — R10 versions, known good
// ============================================================================
__global__ void __launch_bounds__(256) fwd2_kernel(int cur, const float* __restrict__ b2) {
    __shared__ float ws2[288 * 8];
    const int tid = threadIdx.x;
    const int o0 = blockIdx.z * 8;
    for (int i = tid; i < 288; i += 256) {
        const float* src = &g_w2b[i * 64 + o0];
        float* dst = &ws2[i * 8];
#pragma unroll
        for (int r = 0; r < 8; r++) dst[r] = src[r];
    }
    __syncthreads();

    const int bp = blockIdx.x * 256 + tid;
    const int pos = blockIdx.y;
    const int p = pos / 7, q = pos % 7;

    ull acc[8];
#pragma unroll
    for (int r = 0; r < 8; r++) acc[r] = 0ull;

    int off[9];
#pragma unroll
    for (int di = 0; di < 3; di++)
#pragma unroll
        for (int dj = 0; dj < 3; dj++)
            off[di * 3 + dj] = ((2 * p + di) * 16 + (2 * q + dj)) * PB;
    const ull* __restrict__ S1 = (const ull*)g_S1[cur];
#pragma unroll 2
    for (int c = 0; c < 32; c++) {
        const ull* base = S1 + c * 256 * PB + bp;
        const float* wb = ws2 + c * 72;
#pragma unroll
        for (int t = 0; t < 9; t++) {
            ull sv = base[off[t]];
            const float* wp = wb + t * 8;
#pragma unroll
            for (int r = 0; r < 8; r++) acc[r] = fma2(sv, pk(wp[r]), acc[r]);
        }
    }

    ull* __restrict__ outp = (ull*)g_S2[cur ^ 1];
    const int oidx = (o0 * 81 + (p + 1) * 9 + (q + 1)) * PB + bp;
#pragma unroll
    for (int r = 0; r < 8; r++) outp[oidx + r * (81 * PB)] = add2(acc[r], pk(b2[o0 + r]));
}

__global__ void __launch_bounds__(256) fwd3_kernel(int cur, const float* __restrict__ b3) {
    __shared__ ull ws3[576 * 8];
    const int tid = threadIdx.x;
    const int c0 = blockIdx.z * 8;
    const int pos = blockIdx.y;
    for (int i = tid; i < 576; i += 256) {
        const float* src = &g_w3a[i * 64 + c0];
        ull* dst = &ws3[i * 8];
#pragma unroll
        for (int r = 0; r < 8; r++) dst[r] = pk(src[r]);
    }
    __syncthreads();

    const int bp = blockIdx.x * 256 + tid;
    const int p = pos / 7, q = pos % 7;

    ull acc[8];
#pragma unroll
    for (int r = 0; r < 8; r++) acc[r] = 0ull;

    int off[9];
#pragma unroll
    for (int di = 0; di < 3; di++)
#pragma unroll
        for (int dj = 0; dj < 3; dj++)
            off[di * 3 + dj] = ((p + di) * 9 + (q + dj)) * PB;
    const ull* __restrict__ S2 = (const ull*)g_S2[cur];
#pragma unroll 2
    for (int o = 0; o < 64; o++) {
        const ull* base = S2 + o * 81 * PB + bp;
        const ull* wb = ws3 + o * 72;
#pragma unroll
        for (int t = 0; t < 9; t++) {
            ull sv = base[off[t]];
            const ull* wp = wb + t * 8;
#pragma unroll
            for (int r = 0; r < 8; r++) acc[r] = fma2(sv, wp[r], acc[r]);
        }
    }

    ull* __restrict__ outp = (ull*)g_S3[cur ^ 1];
    const int oidx = (c0 * 81 + (p + 1) * 9 + (q + 1)) * PB + bp;
#pragma unroll
    for (int r = 0; r < 8; r++) outp[oidx + r * (81 * PB)] = add2(acc[r], pk(b3[c0 + r]));
}

__global__ void __launch_bounds__(256) fwd4_kernel(int cur, const float* __restrict__ b4) {
    __shared__ ull ws[392 * 8];
    const int tid = threadIdx.x;
    const int j0 = blockIdx.y * 8;
    const int bp = blockIdx.x * 256 + tid;
    const ull* __restrict__ S3 = (const ull*)g_S3[cur];

    ull acc[8];
#pragma unroll
    for (int r = 0; r < 8; r++) acc[r] = 0ull;

    for (int ch = 0; ch < 8; ch++) {
        __syncthreads();
        for (int i = tid; i < 392; i += 256) {
            const float* src = &g_w4t[(ch * 392 + i) * 256 + j0];
            ull* dst = &ws[i * 8];
#pragma unroll
            for (int r = 0; r < 8; r++) dst[r] = pk(src[r]);
        }
        __syncthreads();
        for (int cc = 0; cc < 8; cc++) {
            const ull* cb = S3 + ((ch * 8 + cc) * 81) * PB + bp;
            const ull* wch = ws + cc * 392;
            int kk = 0;
#pragma unroll
            for (int pp = 1; pp <= 7; pp++) {
#pragma unroll
                for (int qq = 1; qq <= 7; qq++) {
                    ull sv = cb[(pp * 9 + qq) * PB];
                    const ull* wp = wch + kk * 8; kk++;
#pragma unroll
                    for (int r = 0; r < 8; r++) acc[r] = fma2(sv, wp[r], acc[r]);
                }
            }
        }
    }

    ull* __restrict__ outp = (ull*)g_S4[cur ^ 1];
#pragma unroll
    for (int r = 0; r < 8; r++) outp[(j0 + r) * PB + bp] = add2(acc[r], pk(b4[j0 + r]));
}

// ---------------- energy readout ----------------
__global__ void energy_zero(float* __restrict__ out) {
    int b = blockIdx.x * 256 + threadIdx.x;
    out[b] = 0.f;
}

__global__ void energy_partial(const float* __restrict__ vb, int fin,
                               float* __restrict__ out) {
    const int b = blockIdx.x * 256 + threadIdx.x;
    const int s = blockIdx.y;  // 0..7
    const float* __restrict__ S1 = g_S1[fin];
    const float* __restrict__ S2 = g_S2[fin];
    const float* __restrict__ S3 = g_S3[fin];
    const float* __restrict__ S4 = g_S4[fin];
    const float* __restrict__ F2 = g_S2[fin ^ 1];
    const float* __restrict__ F3 = g_S3[fin ^ 1];
    const float* __restrict__ F4 = g_S4[fin ^ 1];

    double e = 0.0;
    if (s == 0) {
        for (int p = 0; p < 784; p++) {
            float xv = g_XT[p * BB + b];
            float term = 0.5f * xv * xv - vb[p] * xv;
            e += (double)term;
        }
        for (int i = 0; i < 256; i++) {
            float sv = S4[i * BB + b];
            float term = 0.5f * sv * sv - sv * F4[i * BB + b];
            e += (double)term;
        }
    }
    // S1 interior: 4 channels per slice
    for (int c = s * 4; c < s * 4 + 4; c++) {
        const float* Sr = S1 + c * 256 * BB;
        const float* Dr = g_D1 + c * 256 * BB;
        for (int pp = 1; pp <= 14; pp++)
            for (int vv = 1; vv <= 14; vv++) {
                int ro = (pp * 16 + vv) * BB + b;
                float sv = Sr[ro];
                float term = 0.5f * sv * sv - sv * Dr[ro];
                e += (double)term;
            }
    }
    if (s < 4) {
        for (int c = s * 16; c < s * 16 + 16; c++) {
            const float* Sr = S2 + c * 81 * BB;
            const float* Fr = F2 + c * 81 * BB;
            for (int pp = 1; pp <= 7; pp++)
                for (int qq = 1; qq <= 7; qq++) {
                    int ro = (pp * 9 + qq) * BB + b;
                    float sv = Sr[ro];
                    float term = 0.5f * sv * sv - sv * Fr[ro];
                    e += (double)term;
                }
        }
    } else {
        for (int c = (s - 4) * 16; c < (s - 4) * 16 + 16; c++) {
            const float* Sr = S3 + c * 81 * BB;
            const float* Fr = F3 + c * 81 * BB;
            for (int pp = 1; pp <= 7; pp++)
                for (int qq = 1; qq <= 7; qq++) {
                    int ro = (pp * 9 + qq) * BB + b;
                    float sv = Sr[ro];
                    float term = 0.5f * sv * sv - sv * Fr[ro];
                    e += (double)term;
                }
        }
    }
    atomicAdd(&out[b], (float)e);
}

// ---------------- launcher ----------------
extern "C" void kernel_launch(void* const* d_in, const int* in_sizes, int n_in,
                              void* d_out, int out_size) {
    const float* x  = (const float*)d_in[0];
    const float* vb = (const float*)d_in[1];
    const float* w1 = (const float*)d_in[2];
    const float* b1 = (const float*)d_in[3];
    const float* w2 = (const float*)d_in[4];
    const float* b2 = (const float*)d_in[5];
    const float* w3 = (const float*)d_in[6];
    const float* b3 = (const float*)d_in[7];
    const float* w4 = (const float*)d_in[8];
    const float* b4 = (const float*)d_in[9];
    float* out = (float*)d_out;

    zero_state<<<4096, 256>>>();
    transpose_x<<<dim3(25, 128), dim3(32, 8)>>>(x);
    prep_weights<<<1024, 256>>>(w2, w3, w4);
    compute_d1<<<dim3(16, 196, 32), 256>>>(w1, b1);

    int cur = 0;
    for (int t = 0; t < 50; t++) {
        step_kernel<<<STEP_GRID, 256>>>(cur, b2, b3, b4);
        cur ^= 1;
    }

    // forward-only passes at the fixed point into the free ping-pong buffers
    fwd2_kernel<<<dim3(8, 49, 8), 256>>>(cur, b2);
    fwd3_kernel<<<dim3(8, 49, 8), 256>>>(cur, b3);
    fwd4_kernel<<<dim3(8, 32, 1), 256>>>(cur, b4);

    energy_zero<<<16, 256>>>(out);
    energy_partial<<<dim3(16, 8), 256>>>(vb, cur, out);
}

// round 12
// speedup vs baseline: 1.2023x; 1.2023x over previous
#include <cuda_runtime.h>

#define BB 4096
#define PB 2048   // f32x2 pairs per row (BB/2)

// padded spatial layouts: S1 16x16 (14x14 interior), S2/S3 9x9 (7x7 interior)
constexpr int S1R = 32 * 256;   // 8192 rows
constexpr int S2R = 64 * 81;    // 5184 rows
constexpr int S3R = 64 * 81;
constexpr int S4N = 256;

typedef unsigned long long ull;

// ---------------- packed f32x2 helpers ----------------
__device__ __forceinline__ ull fma2(ull a, ull b, ull c) {
    ull d; asm("fma.rn.f32x2 %0, %1, %2, %3;" : "=l"(d) : "l"(a), "l"(b), "l"(c)); return d;
}
__device__ __forceinline__ ull add2(ull a, ull b) {
    ull d; asm("add.rn.f32x2 %0, %1, %2;" : "=l"(d) : "l"(a), "l"(b)); return d;
}
__device__ __forceinline__ ull mul2(ull a, ull b) {
    ull d; asm("mul.rn.f32x2 %0, %1, %2;" : "=l"(d) : "l"(a), "l"(b)); return d;
}
__device__ __forceinline__ ull pk(float x) {
    ull d; unsigned u = __float_as_uint(x);
    asm("mov.b64 %0, {%1, %1};" : "=l"(d) : "r"(u)); return d;
}
__device__ __forceinline__ ulonglong2 ld2(const ull* p) {
    return *reinterpret_cast<const ulonglong2*>(p);
}
__device__ __forceinline__ void st2(ull* p, ulonglong2 v) {
    *reinterpret_cast<ulonglong2*>(p) = v;
}

// ---------------- scratch (device globals; allocation-free) ----------------
__device__ float g_S1[2][S1R * BB];     // padded [c][16x16][b]
__device__ float g_S2[2][S2R * BB];     // padded [c][9x9][b]
__device__ float g_S3[2][S3R * BB];
__device__ float g_S4[2][S4N * BB];
__device__ float g_D1[S1R * BB];        // conv1(x)+b1, padded like S1
__device__ float g_XT[784 * BB];        // x transposed [pixel][batch], unpadded
__device__ float g_w2a[64 * 9 * 32];    // [o][t][c]
__device__ float g_w2b[32 * 9 * 64];    // [c][t][o]
__device__ float g_w3a[64 * 9 * 64];    // [o][t][m]
__device__ float g_w3b[64 * 9 * 64];    // [m][t][o]
__device__ float g_w4t[3136 * 256];     // [k][j]
__device__ float g_w4r[49 * 256 * 64];  // [pos][j][c]

// ---------------- init / prep ----------------
__global__ void zero_state() {
    int stride = gridDim.x * blockDim.x;
    float4 z = make_float4(0.f, 0.f, 0.f, 0.f);
    const int n1 = S1R * BB / 4;
    const int n2 = S2R * BB / 4;
    const int n4 = S4N * BB / 4;
    for (int i = blockIdx.x * blockDim.x + threadIdx.x; i < n1; i += stride) {
        reinterpret_cast<float4*>(g_S1[0])[i] = z;
        reinterpret_cast<float4*>(g_S1[1])[i] = z;
        reinterpret_cast<float4*>(g_D1)[i] = z;
        if (i < n2) {
            reinterpret_cast<float4*>(g_S2[0])[i] = z;
            reinterpret_cast<float4*>(g_S2[1])[i] = z;
            reinterpret_cast<float4*>(g_S3[0])[i] = z;
            reinterpret_cast<float4*>(g_S3[1])[i] = z;
        }
        if (i < n4) reinterpret_cast<float4*>(g_S4[0])[i] = z;
    }
}

__global__ void transpose_x(const float* __restrict__ x) {
    __shared__ float tile[32][33];
    int p0 = blockIdx.x * 32, b0 = blockIdx.y * 32;
    int tx = threadIdx.x, ty = threadIdx.y;
    for (int i = ty; i < 32; i += 8) {
        int p = p0 + tx;
        tile[i][tx] = (p < 784) ? x[(b0 + i) * 784 + p] : 0.f;
    }
    __syncthreads();
    for (int i = ty; i < 32; i += 8) {
        int p = p0 + i;
        if (p < 784) g_XT[p * BB + b0 + tx] = tile[tx][i];
    }
}

__global__ void prep_weights(const float* __restrict__ w2,
                             const float* __restrict__ w3,
                             const float* __restrict__ w4) {
    int stride = gridDim.x * blockDim.x;
    for (int idx = blockIdx.x * blockDim.x + threadIdx.x; idx < 802816; idx += stride) {
        if (idx < 18432) {  // w2: [o=64][c=32][t=9]
            int o = idx / 288, r = idx % 288, c = r / 9, t = r % 9;
            float v = w2[idx];
            g_w2a[(o * 9 + t) * 32 + c] = v;
            g_w2b[(c * 9 + t) * 64 + o] = v;
        }
        if (idx < 36864) {  // w3: [m=64][o=64][t=9]
            int m = idx / 576, r = idx % 576, o = r / 9, t = r % 9;
            float v = w3[idx];
            g_w3a[(o * 9 + t) * 64 + m] = v;
            g_w3b[(m * 9 + t) * 64 + o] = v;
        }
        {   // w4: [j=256][k=3136]
            int j = idx / 3136, k = idx % 3136;
            float v = w4[idx];
            g_w4t[k * 256 + j] = v;
            int c = k / 49, pos = k % 49;
            g_w4r[(pos * 256 + j) * 64 + c] = v;
        }
    }
}

__global__ void compute_d1(const float* __restrict__ w1, const float* __restrict__ b1) {
    int b = blockIdx.x * 256 + threadIdx.x;
    int pos = blockIdx.y;
    int u = pos / 14, v = pos % 14;
    int c = blockIdx.z;
    float acc = b1[c];
#pragma unroll
    for (int di = 0; di < 3; di++) {
        int h = 2 * u + di - 1;
        if (h < 0 || h >= 28) continue;
#pragma unroll
        for (int dj = 0; dj < 3; dj++) {
            int w = 2 * v + dj - 1;
            if (w < 0 || w >= 28) continue;
            acc = fmaf(w1[c * 9 + di * 3 + dj], g_XT[(h * 28 + w) * BB + b], acc);
        }
    }
    g_D1[(c * 256 + (u + 1) * 16 + (v + 1)) * BB + b] = acc;
}

// ============================================================================
// Fused step: 16 output channels per block (halves L2 input traffic vs 8-wide),
// 4 samples/thread, WEIGHT-duplication packing (R10's proven inner loop, wider).
// Dynamic smem 73728 B = 576 rows x 16 duplicated ull weights.
// acc layout: accA[16] (samples 0-1), accB[16] (samples 2-3).
// Role layout (grid.x = 3200):
//   [0,64): k4    [64,1632): k1    [1632,2416): k2    [2416,3200): k3
// ============================================================================
#define K4_BASE 0
#define K1_BASE 64
#define K2_BASE 1632
#define K3_BASE 2416
#define STEP_GRID 3200
#define STEP_SMEM 73728

// one tap: 2 sample-pairs x 16 channels = 64 MACs, pure LDS + FFMA2
#define ACC16(SV, WP) do {                                                     \
    _Pragma("unroll")                                                          \
    for (int _c = 0; _c < 16; _c++) {                                          \
        ull _w = (WP)[_c];                                                     \
        accA[_c] = fma2((SV).x, _w, accA[_c]);                                 \
        accB[_c] = fma2((SV).y, _w, accB[_c]);                                 \
    }                                                                          \
} while (0)

// stage 16 consecutive floats (64B aligned) global -> 16 duplicated smem ulls
#define STAGE16D(DSTROW, SRCP) do {                                           \
    const float4* _s = reinterpret_cast<const float4*>(SRCP);                  \
    ull* _d = &wsu[(DSTROW) * 16];                                             \
    float4 _a = _s[0], _b = _s[1], _c = _s[2], _e = _s[3];                     \
    _d[0]  = pk(_a.x); _d[1]  = pk(_a.y); _d[2]  = pk(_a.z); _d[3]  = pk(_a.w);\
    _d[4]  = pk(_b.x); _d[5]  = pk(_b.y); _d[6]  = pk(_b.z); _d[7]  = pk(_b.w);\
    _d[8]  = pk(_c.x); _d[9]  = pk(_c.y); _d[10] = pk(_c.z); _d[11] = pk(_c.w);\
    _d[12] = pk(_e.x); _d[13] = pk(_e.y); _d[14] = pk(_e.z); _d[15] = pk(_e.w);\
} while (0)

__global__ void __launch_bounds__(256, 2) step_kernel(int cur,
                                                      const float* __restrict__ b2,
                                                      const float* __restrict__ b3,
                                                      const float* __restrict__ b4) {
    extern __shared__ ull wsu[];   // 576*16 ulls = 73728 B
    const int tid = threadIdx.x;
    const int bx = blockIdx.x;
    const ull half = pk(0.5f);

    ull accA[16], accB[16];
#pragma unroll
    for (int c = 0; c < 16; c++) { accA[c] = 0ull; accB[c] = 0ull; }

    if (bx < K1_BASE) {
        // ---------------- K4: s4' = 0.5*(s4 + W4 s3 + b4) ----------------
        const int bb = bx & 3;
        const int j0 = (bx >> 2) * 16;
        const int u = bb * 512 + 2 * tid;
        const ull* __restrict__ S3 = (const ull*)g_S3[cur];

        for (int ch = 0; ch < 8; ch++) {           // 8 chunks of 8 channels (392 k-rows)
            __syncthreads();
            for (int i = tid; i < 392; i += 256) STAGE16D(i, &g_w4t[(ch * 392 + i) * 256 + j0]);
            __syncthreads();
            for (int cc = 0; cc < 8; cc++) {
                const ull* cb = S3 + ((ch * 8 + cc) * 81) * PB + u;
                const ull* wch = wsu + cc * 49 * 16;
                int kk = 0;
#pragma unroll
                for (int pp = 1; pp <= 7; pp++) {
#pragma unroll
                    for (int qq = 1; qq <= 7; qq++) {
                        ulonglong2 sv = ld2(cb + (pp * 9 + qq) * PB);
                        ACC16(sv, wch + kk * 16); kk++;
                    }
                }
            }
        }

        const ull* __restrict__ S4i = (const ull*)g_S4[cur];
        ull* __restrict__ outp = (ull*)g_S4[cur ^ 1];
#pragma unroll
        for (int c = 0; c < 16; c++) {
            int ii = (j0 + c) * PB + u;
            ull bias = pk(b4[j0 + c]);
            ulonglong2 si = ld2(S4i + ii);
            ulonglong2 o;
            o.x = mul2(add2(add2(si.x, accA[c]), bias), half);
            o.y = mul2(add2(add2(si.y, accB[c]), bias), half);
            st2(outp + ii, o);
        }
    } else if (bx < K2_BASE) {
        // ---------------- K1: s1' = 0.5*(s1 + d1 + tconv2(s2)) ----------------
        int idx = bx - K1_BASE;
        const int bb = idx & 3; idx >>= 2;
        const int pos = idx % 196;
        const int c0 = (idx / 196) * 16;
        const int u_ = bb * 512 + 2 * tid;

        for (int i = tid; i < 576; i += 256) STAGE16D(i, &g_w2a[i * 32 + c0]);
        __syncthreads();

        const int uu = pos / 14, vv = pos % 14;
        // padded S2 row indices; structurally-absent taps -> halo row/col 8 (zeros)
        int p0r, p1r, wu0, wu1;
        if (uu & 1) { p0r = ((uu + 1) >> 1) + 1; wu0 = 0;
                      p1r = ((uu - 1) >> 1) + 1; wu1 = 2; }
        else        { p0r = (uu >> 1) + 1;       wu0 = 1;
                      p1r = 8;                   wu1 = 0; }
        int q0r, q1r, wv0, wv1;
        if (vv & 1) { q0r = ((vv + 1) >> 1) + 1; wv0 = 0;
                      q1r = ((vv - 1) >> 1) + 1; wv1 = 2; }
        else        { q0r = (vv >> 1) + 1;       wv0 = 1;
                      q1r = 8;                   wv1 = 0; }

        const int off00 = (p0r * 9 + q0r) * PB, wr00 = wu0 * 3 + wv0;
        const int off01 = (p0r * 9 + q1r) * PB, wr01 = wu0 * 3 + wv1;
        const int off10 = (p1r * 9 + q0r) * PB, wr10 = wu1 * 3 + wv0;
        const int off11 = (p1r * 9 + q1r) * PB, wr11 = wu1 * 3 + wv1;

        const ull* __restrict__ S2 = (const ull*)g_S2[cur];
#pragma unroll 1
        for (int o = 0; o < 64; o++) {
            const ull* base = S2 + o * 81 * PB + u_;
            const ull* wb = wsu + (o * 9) * 16;
            { ulonglong2 sv = ld2(base + off00); ACC16(sv, wb + wr00 * 16); }
            { ulonglong2 sv = ld2(base + off01); ACC16(sv, wb + wr01 * 16); }
            { ulonglong2 sv = ld2(base + off10); ACC16(sv, wb + wr10 * 16); }
            { ulonglong2 sv = ld2(base + off11); ACC16(sv, wb + wr11 * 16); }
        }

        const ull* __restrict__ S1i = (const ull*)g_S1[cur];
        const ull* __restrict__ D1 = (const ull*)g_D1;
        ull* __restrict__ S1o = (ull*)g_S1[cur ^ 1];
        const int obase = (uu + 1) * 16 + (vv + 1);
#pragma unroll
        for (int c = 0; c < 16; c++) {
            int ii = ((c0 + c) * 256 + obase) * PB + u_;
            ulonglong2 si = ld2(S1i + ii), d1 = ld2(D1 + ii);
            ulonglong2 o;
            o.x = mul2(add2(add2(si.x, d1.x), accA[c]), half);
            o.y = mul2(add2(add2(si.y, d1.y), accB[c]), half);
            st2(S1o + ii, o);
        }
    } else if (bx < K3_BASE) {
        // ---------------- K2: s2' = 0.5*(s2 + conv2(s1)+b2 + tconv3(s3)) ----------------
        int idx = bx - K2_BASE;
        const int bb = idx & 3; idx >>= 2;
        const int pos = idx % 49;
        const int o0 = (idx / 49) * 16;
        const int u_ = bb * 512 + 2 * tid;

        // phase A: conv2 slice (rows 0..287) + tconv3 m=0..31 (rows 288..575)
        for (int i = tid; i < 288; i += 256) STAGE16D(i, &g_w2b[i * 64 + o0]);
        for (int i = tid; i < 288; i += 256) STAGE16D(288 + i, &g_w3b[i * 64 + o0]);
        __syncthreads();

        const int p = pos / 7, q = pos % 7;

        // conv2(s1): stride 2, branchless (padded 16x16)
        {
            int off[9];
#pragma unroll
            for (int di = 0; di < 3; di++)
#pragma unroll
                for (int dj = 0; dj < 3; dj++)
                    off[di * 3 + dj] = ((2 * p + di) * 16 + (2 * q + dj)) * PB;
            const ull* __restrict__ S1 = (const ull*)g_S1[cur];
#pragma unroll 1
            for (int c = 0; c < 32; c++) {
                const ull* base = S1 + c * 256 * PB + u_;
                const ull* wb = wsu + (c * 9) * 16;
#pragma unroll
                for (int t = 0; t < 9; t++) {
                    ulonglong2 sv = ld2(base + off[t]);
                    ACC16(sv, wb + t * 16);
                }
            }
        }
        // tconv3(s3): flipped taps, branchless (padded 9x9)
        {
            int off[9];
#pragma unroll
            for (int di = 0; di < 3; di++)
#pragma unroll
                for (int dj = 0; dj < 3; dj++)
                    off[di * 3 + dj] = ((p + 2 - di) * 9 + (q + 2 - dj)) * PB;
            const ull* __restrict__ S3 = (const ull*)g_S3[cur];
#pragma unroll 1
            for (int m = 0; m < 32; m++) {
                const ull* base = S3 + m * 81 * PB + u_;
                const ull* wb = wsu + (288 + m * 9) * 16;
#pragma unroll
                for (int t = 0; t < 9; t++) {
                    ulonglong2 sv = ld2(base + off[t]);
                    ACC16(sv, wb + t * 16);
                }
            }
            // phase B: reload rows 0..287 with tconv3 m=32..63
            __syncthreads();
            for (int i = tid; i < 288; i += 256) STAGE16D(i, &g_w3b[(288 + i) * 64 + o0]);
            __syncthreads();
#pragma unroll 1
            for (int m = 32; m < 64; m++) {
                const ull* base = S3 + m * 81 * PB + u_;
                const ull* wb = wsu + ((m - 32) * 9) * 16;
#pragma unroll
                for (int t = 0; t < 9; t++) {
                    ulonglong2 sv = ld2(base + off[t]);
                    ACC16(sv, wb + t * 16);
                }
            }
        }

        const ull* __restrict__ S2i = (const ull*)g_S2[cur];
        ull* __restrict__ outp = (ull*)g_S2[cur ^ 1];
        const int obase = (p + 1) * 9 + (q + 1);
#pragma unroll
        for (int c = 0; c < 16; c++) {
            int ii = ((o0 + c) * 81 + obase) * PB + u_;
            ull bias = pk(b2[o0 + c]);
            ulonglong2 si = ld2(S2i + ii);
            ulonglong2 o;
            o.x = mul2(add2(add2(si.x, accA[c]), bias), half);
            o.y = mul2(add2(add2(si.y, accB[c]), bias), half);
            st2(outp + ii, o);
        }
    } else {
        // ---------------- K3: s3' = 0.5*(s3 + conv3(s2)+b3 + W4^T s4) ----------------
        int idx = bx - K3_BASE;
        const int bb = idx & 3; idx >>= 2;
        const int pos = idx % 49;
        const int c0 = (idx / 49) * 16;
        const int u_ = bb * 512 + 2 * tid;

        for (int i = tid; i < 576; i += 256) STAGE16D(i, &g_w3a[i * 64 + c0]);
        __syncthreads();

        const int p = pos / 7, q = pos % 7;

        // conv3(s2): stride 1, branchless (padded 9x9)
        {
            int off[9];
#pragma unroll
            for (int di = 0; di < 3; di++)
#pragma unroll
                for (int dj = 0; dj < 3; dj++)
                    off[di * 3 + dj] = ((p + di) * 9 + (q + dj)) * PB;
            const ull* __restrict__ S2 = (const ull*)g_S2[cur];
#pragma unroll 1
            for (int o = 0; o < 64; o++) {
                const ull* base = S2 + o * 81 * PB + u_;
                const ull* wb = wsu + (o * 9) * 16;
#pragma unroll
                for (int t = 0; t < 9; t++) {
                    ulonglong2 sv = ld2(base + off[t]);
                    ACC16(sv, wb + t * 16);
                }
            }
        }
        // phase B: W4^T s4 (reload smem rows 0..255 with w4r[pos] slice)
        __syncthreads();
        for (int j = tid; j < 256; j += 256) STAGE16D(j, &g_w4r[(pos * 256 + j) * 64 + c0]);
        __syncthreads();
        {
            const ull* __restrict__ S4 = (const ull*)g_S4[cur];
#pragma unroll 1
            for (int j = 0; j < 256; j++) {
                ulonglong2 sv = ld2(S4 + j * PB + u_);
                ACC16(sv, wsu + j * 16);
            }
        }

        const ull* __restrict__ S3i = (const ull*)g_S3[cur];
        ull* __restrict__ outp = (ull*)g_S3[cur ^ 1];
        const int obase = (p + 1) * 9 + (q + 1);
#pragma unroll
        for (int c = 0; c < 16; c++) {
            int ii = ((c0 + c) * 81 + obase) * PB + u_;
            ull bias = pk(b3[c0 + c]);
            ulonglong2 si = ld2(S3i + ii);
            ulonglong2 o;
            o.x = mul2(add2(add2(si.x, accA[c]), bias), half);
            o.y = mul2(add2(add2(si.y, accB[c]), bias), half);
            st2(outp + ii, o);
        }
    }
}

// ============================================================================
// Forward-only kernels for energy readout (run once) — R10 versions, known good
// ============================================================================
__global__ void __launch_bounds__(256) fwd2_kernel(int cur, const float* __restrict__ b2) {
    __shared__ float ws2[288 * 8];
    const int tid = threadIdx.x;
    const int o0 = blockIdx.z * 8;
    for (int i = tid; i < 288; i += 256) {
        const float* src = &g_w2b[i * 64 + o0];
        float* dst = &ws2[i * 8];
#pragma unroll
        for (int r = 0; r < 8; r++) dst[r] = src[r];
    }
    __syncthreads();

    const int bp = blockIdx.x * 256 + tid;
    const int pos = blockIdx.y;
    const int p = pos / 7, q = pos % 7;

    ull acc[8];
#pragma unroll
    for (int r = 0; r < 8; r++) acc[r] = 0ull;

    int off[9];
#pragma unroll
    for (int di = 0; di < 3; di++)
#pragma unroll
        for (int dj = 0; dj < 3; dj++)
            off[di * 3 + dj] = ((2 * p + di) * 16 + (2 * q + dj)) * PB;
    const ull* __restrict__ S1 = (const ull*)g_S1[cur];
#pragma unroll 2
    for (int c = 0; c < 32; c++) {
        const ull* base = S1 + c * 256 * PB + bp;
        const float* wb = ws2 + c * 72;
#pragma unroll
        for (int t = 0; t < 9; t++) {
            ull sv = base[off[t]];
            const float* wp = wb + t * 8;
#pragma unroll
            for (int r = 0; r < 8; r++) acc[r] = fma2(sv, pk(wp[r]), acc[r]);
        }
    }

    ull* __restrict__ outp = (ull*)g_S2[cur ^ 1];
    const int oidx = (o0 * 81 + (p + 1) * 9 + (q + 1)) * PB + bp;
#pragma unroll
    for (int r = 0; r < 8; r++) outp[oidx + r * (81 * PB)] = add2(acc[r], pk(b2[o0 + r]));
}

__global__ void __launch_bounds__(256) fwd3_kernel(int cur, const float* __restrict__ b3) {
    __shared__ ull ws3[576 * 8];
    const int tid = threadIdx.x;
    const int c0 = blockIdx.z * 8;
    const int pos = blockIdx.y;
    for (int i = tid; i < 576; i += 256) {
        const float* src = &g_w3a[i * 64 + c0];
        ull* dst = &ws3[i * 8];
#pragma unroll
        for (int r = 0; r < 8; r++) dst[r] = pk(src[r]);
    }
    __syncthreads();

    const int bp = blockIdx.x * 256 + tid;
    const int p = pos / 7, q = pos % 7;

    ull acc[8];
#pragma unroll
    for (int r = 0; r < 8; r++) acc[r] = 0ull;

    int off[9];
#pragma unroll
    for (int di = 0; di < 3; di++)
#pragma unroll
        for (int dj = 0; dj < 3; dj++)
            off[di * 3 + dj] = ((p + di) * 9 + (q + dj)) * PB;
    const ull* __restrict__ S2 = (const ull*)g_S2[cur];
#pragma unroll 2
    for (int o = 0; o < 64; o++) {
        const ull* base = S2 + o * 81 * PB + bp;
        const ull* wb = ws3 + o * 72;
#pragma unroll
        for (int t = 0; t < 9; t++) {
            ull sv = base[off[t]];
            const ull* wp = wb + t * 8;
#pragma unroll
            for (int r = 0; r < 8; r++) acc[r] = fma2(sv, wp[r], acc[r]);
        }
    }

    ull* __restrict__ outp = (ull*)g_S3[cur ^ 1];
    const int oidx = (c0 * 81 + (p + 1) * 9 + (q + 1)) * PB + bp;
#pragma unroll
    for (int r = 0; r < 8; r++) outp[oidx + r * (81 * PB)] = add2(acc[r], pk(b3[c0 + r]));
}

__global__ void __launch_bounds__(256) fwd4_kernel(int cur, const float* __restrict__ b4) {
    __shared__ ull ws[392 * 8];
    const int tid = threadIdx.x;
    const int j0 = blockIdx.y * 8;
    const int bp = blockIdx.x * 256 + tid;
    const ull* __restrict__ S3 = (const ull*)g_S3[cur];

    ull acc[8];
#pragma unroll
    for (int r = 0; r < 8; r++) acc[r] = 0ull;

    for (int ch = 0; ch < 8; ch++) {
        __syncthreads();
        for (int i = tid; i < 392; i += 256) {
            const float* src = &g_w4t[(ch * 392 + i) * 256 + j0];
            ull* dst = &ws[i * 8];
#pragma unroll
            for (int r = 0; r < 8; r++) dst[r] = pk(src[r]);
        }
        __syncthreads();
        for (int cc = 0; cc < 8; cc++) {
            const ull* cb = S3 + ((ch * 8 + cc) * 81) * PB + bp;
            const ull* wch = ws + cc * 392;
            int kk = 0;
#pragma unroll
            for (int pp = 1; pp <= 7; pp++) {
#pragma unroll
                for (int qq = 1; qq <= 7; qq++) {
                    ull sv = cb[(pp * 9 + qq) * PB];
                    const ull* wp = wch + kk * 8; kk++;
#pragma unroll
                    for (int r = 0; r < 8; r++) acc[r] = fma2(sv, wp[r], acc[r]);
                }
            }
        }
    }

    ull* __restrict__ outp = (ull*)g_S4[cur ^ 1];
#pragma unroll
    for (int r = 0; r < 8; r++) outp[(j0 + r) * PB + bp] = add2(acc[r], pk(b4[j0 + r]));
}

// ---------------- energy readout ----------------
__global__ void energy_zero(float* __restrict__ out) {
    int b = blockIdx.x * 256 + threadIdx.x;
    out[b] = 0.f;
}

__global__ void energy_partial(const float* __restrict__ vb, int fin,
                               float* __restrict__ out) {
    const int b = blockIdx.x * 256 + threadIdx.x;
    const int s = blockIdx.y;  // 0..7
    const float* __restrict__ S1 = g_S1[fin];
    const float* __restrict__ S2 = g_S2[fin];
    const float* __restrict__ S3 = g_S3[fin];
    const float* __restrict__ S4 = g_S4[fin];
    const float* __restrict__ F2 = g_S2[fin ^ 1];
    const float* __restrict__ F3 = g_S3[fin ^ 1];
    const float* __restrict__ F4 = g_S4[fin ^ 1];

    double e = 0.0;
    if (s == 0) {
        for (int p = 0; p < 784; p++) {
            float xv = g_XT[p * BB + b];
            float term = 0.5f * xv * xv - vb[p] * xv;
            e += (double)term;
        }
        for (int i = 0; i < 256; i++) {
            float sv = S4[i * BB + b];
            float term = 0.5f * sv * sv - sv * F4[i * BB + b];
            e += (double)term;
        }
    }
    // S1 interior: 4 channels per slice
    for (int c = s * 4; c < s * 4 + 4; c++) {
        const float* Sr = S1 + c * 256 * BB;
        const float* Dr = g_D1 + c * 256 * BB;
        for (int pp = 1; pp <= 14; pp++)
            for (int vv = 1; vv <= 14; vv++) {
                int ro = (pp * 16 + vv) * BB + b;
                float sv = Sr[ro];
                float term = 0.5f * sv * sv - sv * Dr[ro];
                e += (double)term;
            }
    }
    if (s < 4) {
        for (int c = s * 16; c < s * 16 + 16; c++) {
            const float* Sr = S2 + c * 81 * BB;
            const float* Fr = F2 + c * 81 * BB;
            for (int pp = 1; pp <= 7; pp++)
                for (int qq = 1; qq <= 7; qq++) {
                    int ro = (pp * 9 + qq) * BB + b;
                    float sv = Sr[ro];
                    float term = 0.5f * sv * sv - sv * Fr[ro];
                    e += (double)term;
                }
        }
    } else {
        for (int c = (s - 4) * 16; c < (s - 4) * 16 + 16; c++) {
            const float* Sr = S3 + c * 81 * BB;
            const float* Fr = F3 + c * 81 * BB;
            for (int pp = 1; pp <= 7; pp++)
                for (int qq = 1; qq <= 7; qq++) {
                    int ro = (pp * 9 + qq) * BB + b;
                    float sv = Sr[ro];
                    float term = 0.5f * sv * sv - sv * Fr[ro];
                    e += (double)term;
                }
        }
    }
    atomicAdd(&out[b], (float)e);
}

// ---------------- launcher ----------------
extern "C" void kernel_launch(void* const* d_in, const int* in_sizes, int n_in,
                              void* d_out, int out_size) {
    const float* x  = (const float*)d_in[0];
    const float* vb = (const float*)d_in[1];
    const float* w1 = (const float*)d_in[2];
    const float* b1 = (const float*)d_in[3];
    const float* w2 = (const float*)d_in[4];
    const float* b2 = (const float*)d_in[5];
    const float* w3 = (const float*)d_in[6];
    const float* b3 = (const float*)d_in[7];
    const float* w4 = (const float*)d_in[8];
    const float* b4 = (const float*)d_in[9];
    float* out = (float*)d_out;

    cudaFuncSetAttribute(step_kernel, cudaFuncAttributeMaxDynamicSharedMemorySize, STEP_SMEM);

    zero_state<<<4096, 256>>>();
    transpose_x<<<dim3(25, 128), dim3(32, 8)>>>(x);
    prep_weights<<<1024, 256>>>(w2, w3, w4);
    compute_d1<<<dim3(16, 196, 32), 256>>>(w1, b1);

    int cur = 0;
    for (int t = 0; t < 50; t++) {
        step_kernel<<<STEP_GRID, 256, STEP_SMEM>>>(cur, b2, b3, b4);
        cur ^= 1;
    }

    // forward-only passes at the fixed point into the free ping-pong buffers
    fwd2_kernel<<<dim3(8, 49, 8), 256>>>(cur, b2);
    fwd3_kernel<<<dim3(8, 49, 8), 256>>>(cur, b3);
    fwd4_kernel<<<dim3(8, 32, 1), 256>>>(cur, b4);

    energy_zero<<<16, 256>>>(out);
    energy_partial<<<dim3(16, 8), 256>>>(vb, cur, out);
}

// round 14
// speedup vs baseline: 3.5777x; 2.9758x over previous
#include <cuda_runtime.h>

#define BB 4096
#define PB 2048    // big-batch f32x2 pairs
#define BBS 1024   // small (basis) batch: 784 basis + 1 zero + pad
#define PBS 512

// padded spatial layouts: S1 16x16 (14x14 interior), S2/S3 9x9 (7x7 interior)
constexpr int S1R = 32 * 256;   // 8192 rows
constexpr int S2R = 64 * 81;    // 5184 rows
constexpr int S4N = 256;
constexpr int RTOT = S1R + S2R + S2R + S4N;   // 18816 padded state rows

typedef unsigned long long ull;

// ---------------- packed f32x2 helpers ----------------
__device__ __forceinline__ ull fma2(ull a, ull b, ull c) {
    ull d; asm("fma.rn.f32x2 %0, %1, %2, %3;" : "=l"(d) : "l"(a), "l"(b), "l"(c)); return d;
}
__device__ __forceinline__ ull add2(ull a, ull b) {
    ull d; asm("add.rn.f32x2 %0, %1, %2;" : "=l"(d) : "l"(a), "l"(b)); return d;
}
__device__ __forceinline__ ull mul2(ull a, ull b) {
    ull d; asm("mul.rn.f32x2 %0, %1, %2;" : "=l"(d) : "l"(a), "l"(b)); return d;
}
__device__ __forceinline__ ull pk(float x) {
    ull d; unsigned u = __float_as_uint(x);
    asm("mov.b64 %0, {%1, %1};" : "=l"(d) : "r"(u)); return d;
}
__device__ __forceinline__ ulonglong2 ld2(const ull* p) {
    return *reinterpret_cast<const ulonglong2*>(p);
}
__device__ __forceinline__ void st2(ull* p, ulonglong2 v) {
    *reinterpret_cast<ulonglong2*>(p) = v;
}

// ---------------- scratch (device globals; allocation-free) ----------------
// big-batch state (filled by expand GEMM; [1] holds forward results)
__device__ float g_S1[2][S1R * BB];
__device__ float g_S2[2][S2R * BB];
__device__ float g_S3[2][S2R * BB];
__device__ float g_S4[2][S4N * BB];
__device__ float g_D1[S1R * BB];        // conv1(x)+b1, big batch (energy only)
__device__ float g_XT[784 * BB];        // x transposed [pixel][batch]
// small (basis) relaxation state
__device__ float g_T1[2][S1R * BBS];
__device__ float g_T2[2][S2R * BBS];
__device__ float g_T3[2][S2R * BBS];
__device__ float g_T4[2][S4N * BBS];
__device__ float g_TD1[S1R * BBS];
__device__ float g_XTs[784 * BBS];
// linear map  s50(x) = MM·x + m0
__device__ float g_MM[RTOT * 784];
__device__ float g_M0[RTOT];
// weight layouts
__device__ float g_w2a[64 * 9 * 32];    // [o][t][c]
__device__ float g_w2b[32 * 9 * 64];    // [c][t][o]
__device__ float g_w3a[64 * 9 * 64];    // [o][t][m]
__device__ float g_w3b[64 * 9 * 64];    // [m][t][o]
__device__ float g_w4t[3136 * 256];     // [k][j]
__device__ float g_w4r[49 * 256 * 64];  // [pos][j][c]

// ---------------- init / prep ----------------
__global__ void zero_small() {
    int stride = gridDim.x * blockDim.x;
    float4 z = make_float4(0.f, 0.f, 0.f, 0.f);
    const int n1 = S1R * BBS / 4;
    const int n2 = S2R * BBS / 4;
    const int n4 = S4N * BBS / 4;
    for (int i = blockIdx.x * blockDim.x + threadIdx.x; i < n1; i += stride) {
        reinterpret_cast<float4*>(g_T1[0])[i] = z;
        reinterpret_cast<float4*>(g_T1[1])[i] = z;
        reinterpret_cast<float4*>(g_TD1)[i] = z;
        if (i < n2) {
            reinterpret_cast<float4*>(g_T2[0])[i] = z;
            reinterpret_cast<float4*>(g_T2[1])[i] = z;
            reinterpret_cast<float4*>(g_T3[0])[i] = z;
            reinterpret_cast<float4*>(g_T3[1])[i] = z;
        }
        if (i < n4) {
            reinterpret_cast<float4*>(g_T4[0])[i] = z;
            reinterpret_cast<float4*>(g_T4[1])[i] = z;
        }
    }
}

__global__ void basis_x() {
    int idx = blockIdx.x * 256 + threadIdx.x;       // over 784*BBS
    if (idx >= 784 * BBS) return;
    int p = idx / BBS, c = idx % BBS;
    g_XTs[idx] = (c < 784 && p == c) ? 1.f : 0.f;
}

__global__ void transpose_x(const float* __restrict__ x) {
    __shared__ float tile[32][33];
    int p0 = blockIdx.x * 32, b0 = blockIdx.y * 32;
    int tx = threadIdx.x, ty = threadIdx.y;
    for (int i = ty; i < 32; i += 8) {
        int p = p0 + tx;
        tile[i][tx] = (p < 784) ? x[(b0 + i) * 784 + p] : 0.f;
    }
    __syncthreads();
    for (int i = ty; i < 32; i += 8) {
        int p = p0 + i;
        if (p < 784) g_XT[p * BB + b0 + tx] = tile[tx][i];
    }
}

__global__ void prep_weights(const float* __restrict__ w2,
                             const float* __restrict__ w3,
                             const float* __restrict__ w4) {
    int stride = gridDim.x * blockDim.x;
    for (int idx = blockIdx.x * blockDim.x + threadIdx.x; idx < 802816; idx += stride) {
        if (idx < 18432) {  // w2: [o=64][c=32][t=9]
            int o = idx / 288, r = idx % 288, c = r / 9, t = r % 9;
            float v = w2[idx];
            g_w2a[(o * 9 + t) * 32 + c] = v;
            g_w2b[(c * 9 + t) * 64 + o] = v;
        }
        if (idx < 36864) {  // w3: [m=64][o=64][t=9]
            int m = idx / 576, r = idx % 576, o = r / 9, t = r % 9;
            float v = w3[idx];
            g_w3a[(o * 9 + t) * 64 + m] = v;
            g_w3b[(m * 9 + t) * 64 + o] = v;
        }
        {   // w4: [j=256][k=3136]
            int j = idx / 3136, k = idx % 3136;
            float v = w4[idx];
            g_w4t[k * 256 + j] = v;
            int c = k / 49, pos = k % 49;
            g_w4r[(pos * 256 + j) * 64 + c] = v;
        }
    }
}

// d1 = conv1(x)+b1 — small (basis) batch, globals referenced device-side
__global__ void compute_d1_small(const float* __restrict__ w1, const float* __restrict__ b1) {
    int b = blockIdx.x * 256 + threadIdx.x;
    int pos = blockIdx.y;
    int u = pos / 14, v = pos % 14;
    int c = blockIdx.z;
    float acc = b1[c];
#pragma unroll
    for (int di = 0; di < 3; di++) {
        int h = 2 * u + di - 1;
        if (h < 0 || h >= 28) continue;
#pragma unroll
        for (int dj = 0; dj < 3; dj++) {
            int w = 2 * v + dj - 1;
            if (w < 0 || w >= 28) continue;
            acc = fmaf(w1[c * 9 + di * 3 + dj], g_XTs[(h * 28 + w) * BBS + b], acc);
        }
    }
    g_TD1[(c * 256 + (u + 1) * 16 + (v + 1)) * BBS + b] = acc;
}

// d1 = conv1(x)+b1 — big batch (energy epilogue)
__global__ void compute_d1_big(const float* __restrict__ w1, const float* __restrict__ b1) {
    int b = blockIdx.x * 256 + threadIdx.x;
    int pos = blockIdx.y;
    int u = pos / 14, v = pos % 14;
    int c = blockIdx.z;
    float acc = b1[c];
#pragma unroll
    for (int di = 0; di < 3; di++) {
        int h = 2 * u + di - 1;
        if (h < 0 || h >= 28) continue;
#pragma unroll
        for (int dj = 0; dj < 3; dj++) {
            int w = 2 * v + dj - 1;
            if (w < 0 || w >= 28) continue;
            acc = fmaf(w1[c * 9 + di * 3 + dj], g_XT[(h * 28 + w) * BB + b], acc);
        }
    }
    g_D1[(c * 256 + (u + 1) * 16 + (v + 1)) * BB + b] = acc;
}

// ============================================================================
// Fused relaxation step on the BASIS batch (PBS=512 pairs), R12-proven loops.
// 16 output channels/block, 4 samples/thread, dynamic smem 73728 B.
// Grid = 800: [0,16): k4   [16,408): k1   [408,604): k2   [604,800): k3
// All state accessed via g_T*[cur] INSIDE the kernel (no host symbols).
// ============================================================================
#define STEP_SMEM 73728

#define ACC16(SV, WP) do {                                                     \
    _Pragma("unroll")                                                          \
    for (int _c = 0; _c < 16; _c++) {                                          \
        ull _w = (WP)[_c];                                                     \
        accA[_c] = fma2((SV).x, _w, accA[_c]);                                 \
        accB[_c] = fma2((SV).y, _w, accB[_c]);                                 \
    }                                                                          \
} while (0)

#define STAGE16D(DSTROW, SRCP) do {                                           \
    const float4* _s = reinterpret_cast<const float4*>(SRCP);                  \
    ull* _d = &wsu[(DSTROW) * 16];                                             \
    float4 _a = _s[0], _b = _s[1], _c = _s[2], _e = _s[3];                     \
    _d[0]  = pk(_a.x); _d[1]  = pk(_a.y); _d[2]  = pk(_a.z); _d[3]  = pk(_a.w);\
    _d[4]  = pk(_b.x); _d[5]  = pk(_b.y); _d[6]  = pk(_b.z); _d[7]  = pk(_b.w);\
    _d[8]  = pk(_c.x); _d[9]  = pk(_c.y); _d[10] = pk(_c.z); _d[11] = pk(_c.w);\
    _d[12] = pk(_e.x); _d[13] = pk(_e.y); _d[14] = pk(_e.z); _d[15] = pk(_e.w);\
} while (0)

__global__ void __launch_bounds__(256, 2) step_small(int cur,
                                                     const float* __restrict__ b2,
                                                     const float* __restrict__ b3,
                                                     const float* __restrict__ b4) {
    extern __shared__ ull wsu[];   // 576*16 ulls
    const int tid = threadIdx.x;
    const int bx = blockIdx.x;
    const ull half = pk(0.5f);

    const ull* __restrict__ S1c = (const ull*)g_T1[cur];
    ull* __restrict__ S1n = (ull*)g_T1[cur ^ 1];
    const ull* __restrict__ S2c = (const ull*)g_T2[cur];
    ull* __restrict__ S2n = (ull*)g_T2[cur ^ 1];
    const ull* __restrict__ S3c = (const ull*)g_T3[cur];
    ull* __restrict__ S3n = (ull*)g_T3[cur ^ 1];
    const ull* __restrict__ S4c = (const ull*)g_T4[cur];
    ull* __restrict__ S4n = (ull*)g_T4[cur ^ 1];
    const ull* __restrict__ D1p = (const ull*)g_TD1;

    ull accA[16], accB[16];
#pragma unroll
    for (int c = 0; c < 16; c++) { accA[c] = 0ull; accB[c] = 0ull; }

    if (bx < 16) {
        // ---------------- K4: s4' = 0.5*(s4 + W4 s3 + b4) ----------------
        const int j0 = bx * 16;
        const int u = 2 * tid;

        for (int ch = 0; ch < 8; ch++) {
            __syncthreads();
            for (int i = tid; i < 392; i += 256) STAGE16D(i, &g_w4t[(ch * 392 + i) * 256 + j0]);
            __syncthreads();
            for (int cc = 0; cc < 8; cc++) {
                const ull* cb = S3c + ((ch * 8 + cc) * 81) * PBS + u;
                const ull* wch = wsu + cc * 49 * 16;
                int kk = 0;
#pragma unroll
                for (int pp = 1; pp <= 7; pp++) {
#pragma unroll
                    for (int qq = 1; qq <= 7; qq++) {
                        ulonglong2 sv = ld2(cb + (pp * 9 + qq) * PBS);
                        ACC16(sv, wch + kk * 16); kk++;
                    }
                }
            }
        }

#pragma unroll
        for (int c = 0; c < 16; c++) {
            int ii = (j0 + c) * PBS + u;
            ull bias = pk(b4[j0 + c]);
            ulonglong2 si = ld2(S4c + ii);
            ulonglong2 o;
            o.x = mul2(add2(add2(si.x, accA[c]), bias), half);
            o.y = mul2(add2(add2(si.y, accB[c]), bias), half);
            st2(S4n + ii, o);
        }
    } else if (bx < 408) {
        // ---------------- K1: s1' = 0.5*(s1 + d1 + tconv2(s2)) ----------------
        int t = bx - 16;
        const int pos = t % 196;
        const int c0 = (t / 196) * 16;
        const int u_ = 2 * tid;

        for (int i = tid; i < 576; i += 256) STAGE16D(i, &g_w2a[i * 32 + c0]);
        __syncthreads();

        const int uu = pos / 14, vv = pos % 14;
        int p0r, p1r, wu0, wu1;
        if (uu & 1) { p0r = ((uu + 1) >> 1) + 1; wu0 = 0;
                      p1r = ((uu - 1) >> 1) + 1; wu1 = 2; }
        else        { p0r = (uu >> 1) + 1;       wu0 = 1;
                      p1r = 8;                   wu1 = 0; }
        int q0r, q1r, wv0, wv1;
        if (vv & 1) { q0r = ((vv + 1) >> 1) + 1; wv0 = 0;
                      q1r = ((vv - 1) >> 1) + 1; wv1 = 2; }
        else        { q0r = (vv >> 1) + 1;       wv0 = 1;
                      q1r = 8;                   wv1 = 0; }

        const int off00 = (p0r * 9 + q0r) * PBS, wr00 = wu0 * 3 + wv0;
        const int off01 = (p0r * 9 + q1r) * PBS, wr01 = wu0 * 3 + wv1;
        const int off10 = (p1r * 9 + q0r) * PBS, wr10 = wu1 * 3 + wv0;
        const int off11 = (p1r * 9 + q1r) * PBS, wr11 = wu1 * 3 + wv1;

#pragma unroll 1
        for (int o = 0; o < 64; o++) {
            const ull* base = S2c + o * 81 * PBS + u_;
            const ull* wb = wsu + (o * 9) * 16;
            { ulonglong2 sv = ld2(base + off00); ACC16(sv, wb + wr00 * 16); }
            { ulonglong2 sv = ld2(base + off01); ACC16(sv, wb + wr01 * 16); }
            { ulonglong2 sv = ld2(base + off10); ACC16(sv, wb + wr10 * 16); }
            { ulonglong2 sv = ld2(base + off11); ACC16(sv, wb + wr11 * 16); }
        }

        const int obase = (uu + 1) * 16 + (vv + 1);
#pragma unroll
        for (int c = 0; c < 16; c++) {
            int ii = ((c0 + c) * 256 + obase) * PBS + u_;
            ulonglong2 si = ld2(S1c + ii), d1 = ld2(D1p + ii);
            ulonglong2 o;
            o.x = mul2(add2(add2(si.x, d1.x), accA[c]), half);
            o.y = mul2(add2(add2(si.y, d1.y), accB[c]), half);
            st2(S1n + ii, o);
        }
    } else if (bx < 604) {
        // ---------------- K2: s2' = 0.5*(s2 + conv2(s1)+b2 + tconv3(s3)) ----------------
        int t = bx - 408;
        const int pos = t % 49;
        const int o0 = (t / 49) * 16;
        const int u_ = 2 * tid;

        for (int i = tid; i < 288; i += 256) STAGE16D(i, &g_w2b[i * 64 + o0]);
        for (int i = tid; i < 288; i += 256) STAGE16D(288 + i, &g_w3b[i * 64 + o0]);
        __syncthreads();

        const int p = pos / 7, q = pos % 7;

        // conv2(s1): stride 2, branchless (padded 16x16)
        {
            int off[9];
#pragma unroll
            for (int di = 0; di < 3; di++)
#pragma unroll
                for (int dj = 0; dj < 3; dj++)
                    off[di * 3 + dj] = ((2 * p + di) * 16 + (2 * q + dj)) * PBS;
#pragma unroll 1
            for (int c = 0; c < 32; c++) {
                const ull* base = S1c + c * 256 * PBS + u_;
                const ull* wb = wsu + (c * 9) * 16;
#pragma unroll
                for (int t2 = 0; t2 < 9; t2++) {
                    ulonglong2 sv = ld2(base + off[t2]);
                    ACC16(sv, wb + t2 * 16);
                }
            }
        }
        // tconv3(s3): flipped taps, branchless (padded 9x9)
        {
            int off[9];
#pragma unroll
            for (int di = 0; di < 3; di++)
#pragma unroll
                for (int dj = 0; dj < 3; dj++)
                    off[di * 3 + dj] = ((p + 2 - di) * 9 + (q + 2 - dj)) * PBS;
#pragma unroll 1
            for (int m = 0; m < 32; m++) {
                const ull* base = S3c + m * 81 * PBS + u_;
                const ull* wb = wsu + (288 + m * 9) * 16;
#pragma unroll
                for (int t2 = 0; t2 < 9; t2++) {
                    ulonglong2 sv = ld2(base + off[t2]);
                    ACC16(sv, wb + t2 * 16);
                }
            }
            __syncthreads();
            for (int i = tid; i < 288; i += 256) STAGE16D(i, &g_w3b[(288 + i) * 64 + o0]);
            __syncthreads();
#pragma unroll 1
            for (int m = 32; m < 64; m++) {
                const ull* base = S3c + m * 81 * PBS + u_;
                const ull* wb = wsu + ((m - 32) * 9) * 16;
#pragma unroll
                for (int t2 = 0; t2 < 9; t2++) {
                    ulonglong2 sv = ld2(base + off[t2]);
                    ACC16(sv, wb + t2 * 16);
                }
            }
        }

        const int obase = (p + 1) * 9 + (q + 1);
#pragma unroll
        for (int c = 0; c < 16; c++) {
            int ii = ((o0 + c) * 81 + obase) * PBS + u_;
            ull bias = pk(b2[o0 + c]);
            ulonglong2 si = ld2(S2c + ii);
            ulonglong2 o;
            o.x = mul2(add2(add2(si.x, accA[c]), bias), half);
            o.y = mul2(add2(add2(si.y, accB[c]), bias), half);
            st2(S2n + ii, o);
        }
    } else {
        // ---------------- K3: s3' = 0.5*(s3 + conv3(s2)+b3 + W4^T s4) ----------------
        int t = bx - 604;
        const int pos = t % 49;
        const int c0 = (t / 49) * 16;
        const int u_ = 2 * tid;

        for (int i = tid; i < 576; i += 256) STAGE16D(i, &g_w3a[i * 64 + c0]);
        __syncthreads();

        const int p = pos / 7, q = pos % 7;

        // conv3(s2): stride 1, branchless (padded 9x9)
        {
            int off[9];
#pragma unroll
            for (int di = 0; di < 3; di++)
#pragma unroll
                for (int dj = 0; dj < 3; dj++)
                    off[di * 3 + dj] = ((p + di) * 9 + (q + dj)) * PBS;
#pragma unroll 1
            for (int o = 0; o < 64; o++) {
                const ull* base = S2c + o * 81 * PBS + u_;
                const ull* wb = wsu + (o * 9) * 16;
#pragma unroll
                for (int t2 = 0; t2 < 9; t2++) {
                    ulonglong2 sv = ld2(base + off[t2]);
                    ACC16(sv, wb + t2 * 16);
                }
            }
        }
        __syncthreads();
        for (int j = tid; j < 256; j += 256) STAGE16D(j, &g_w4r[(pos * 256 + j) * 64 + c0]);
        __syncthreads();
        {
#pragma unroll 1
            for (int j = 0; j < 256; j++) {
                ulonglong2 sv = ld2(S4c + j * PBS + u_);
                ACC16(sv, wsu + j * 16);
            }
        }

        const int obase = (p + 1) * 9 + (q + 1);
#pragma unroll
        for (int c = 0; c < 16; c++) {
            int ii = ((c0 + c) * 81 + obase) * PBS + u_;
            ull bias = pk(b3[c0 + c]);
            ulonglong2 si = ld2(S3c + ii);
            ulonglong2 o;
            o.x = mul2(add2(add2(si.x, accA[c]), bias), half);
            o.y = mul2(add2(add2(si.y, accB[c]), bias), half);
            st2(S3n + ii, o);
        }
    }
}

// ---------------- MM / m0 extraction (final state lives in buffer [0]) ------
__device__ __forceinline__ float small_read(int r, int c) {
    if (r < S1R) return g_T1[0][r * BBS + c];
    if (r < S1R + S2R) return g_T2[0][(r - S1R) * BBS + c];
    if (r < S1R + 2 * S2R) return g_T3[0][(r - S1R - S2R) * BBS + c];
    return g_T4[0][(r - S1R - 2 * S2R) * BBS + c];
}

__global__ void build_mm() {
    int idx = blockIdx.x * 256 + threadIdx.x;   // over RTOT*784
    if (idx >= RTOT * 784) return;
    int r = idx / 784, i = idx % 784;
    float m0 = small_read(r, 784);
    g_MM[idx] = small_read(r, i) - m0;
    if (i == 0) g_M0[r] = m0;
}

// ---------------- expand GEMM: state[r][b] = sum_i MM[r][i]*x[i][b] + m0[r] ----
// grid: (RTOT/16) row-blocks x 4 batch-slices; 16 rows x 1024 samples per block
__global__ void __launch_bounds__(256) expand_kernel() {
    __shared__ ull smw[196 * 16];    // 25088 B (k-major, 16 rows per k)
    __shared__ float m0s[16];
    const int tid = threadIdx.x;
    const int bx = blockIdx.x;
    const int bslice = bx & 3;
    const int row0 = (bx >> 2) * 16;
    const int u = bslice * 512 + 2 * tid;

    if (tid < 16) m0s[tid] = g_M0[row0 + tid];
    __syncthreads();

    ull accA[16], accB[16];
#pragma unroll
    for (int c = 0; c < 16; c++) { accA[c] = pk(m0s[c]); accB[c] = accA[c]; }

    const ull* __restrict__ XT2 = (const ull*)g_XT;
    for (int ch = 0; ch < 4; ch++) {
        __syncthreads();
        for (int idx = tid; idx < 16 * 196; idx += 256) {
            int r = idx / 196, k = idx % 196;
            smw[k * 16 + r] = pk(g_MM[(row0 + r) * 784 + ch * 196 + k]);
        }
        __syncthreads();
#pragma unroll 1
        for (int k = 0; k < 196; k++) {
            ulonglong2 sv = ld2(XT2 + (ch * 196 + k) * PB + u);
            const ull* wp = &smw[k * 16];
            ACC16(sv, wp);
        }
    }

    ull* dst; int base;
    if (row0 < S1R)                { dst = (ull*)g_S1[0]; base = 0; }
    else if (row0 < S1R + S2R)     { dst = (ull*)g_S2[0]; base = S1R; }
    else if (row0 < S1R + 2 * S2R) { dst = (ull*)g_S3[0]; base = S1R + S2R; }
    else                           { dst = (ull*)g_S4[0]; base = S1R + 2 * S2R; }
#pragma unroll
    for (int c = 0; c < 16; c++) {
        ulonglong2 o; o.x = accA[c]; o.y = accB[c];
        st2(dst + ((row0 - base + c) * PB + u), o);
    }
}

// ============================================================================
// Forward-only kernels for energy readout (big batch) — R10/R12 proven
// ============================================================================
__global__ void __launch_bounds__(256) fwd2_kernel(int cur, const float* __restrict__ b2) {
    __shared__ float ws2[288 * 8];
    const int tid = threadIdx.x;
    const int o0 = blockIdx.z * 8;
    for (int i = tid; i < 288; i += 256) {
        const float* src = &g_w2b[i * 64 + o0];
        float* dst = &ws2[i * 8];
#pragma unroll
        for (int r = 0; r < 8; r++) dst[r] = src[r];
    }
    __syncthreads();

    const int bp = blockIdx.x * 256 + tid;
    const int pos = blockIdx.y;
    const int p = pos / 7, q = pos % 7;

    ull acc[8];
#pragma unroll
    for (int r = 0; r < 8; r++) acc[r] = 0ull;

    int off[9];
#pragma unroll
    for (int di = 0; di < 3; di++)
#pragma unroll
        for (int dj = 0; dj < 3; dj++)
            off[di * 3 + dj] = ((2 * p + di) * 16 + (2 * q + dj)) * PB;
    const ull* __restrict__ S1 = (const ull*)g_S1[cur];
#pragma unroll 2
    for (int c = 0; c < 32; c++) {
        const ull* base = S1 + c * 256 * PB + bp;
        const float* wb = ws2 + c * 72;
#pragma unroll
        for (int t = 0; t < 9; t++) {
            ull sv = base[off[t]];
            const float* wp = wb + t * 8;
#pragma unroll
            for (int r = 0; r < 8; r++) acc[r] = fma2(sv, pk(wp[r]), acc[r]);
        }
    }

    ull* __restrict__ outp = (ull*)g_S2[cur ^ 1];
    const int oidx = (o0 * 81 + (p + 1) * 9 + (q + 1)) * PB + bp;
#pragma unroll
    for (int r = 0; r < 8; r++) outp[oidx + r * (81 * PB)] = add2(acc[r], pk(b2[o0 + r]));
}

__global__ void __launch_bounds__(256) fwd3_kernel(int cur, const float* __restrict__ b3) {
    __shared__ ull ws3[576 * 8];
    const int tid = threadIdx.x;
    const int c0 = blockIdx.z * 8;
    const int pos = blockIdx.y;
    for (int i = tid; i < 576; i += 256) {
        const float* src = &g_w3a[i * 64 + c0];
        ull* dst = &ws3[i * 8];
#pragma unroll
        for (int r = 0; r < 8; r++) dst[r] = pk(src[r]);
    }
    __syncthreads();

    const int bp = blockIdx.x * 256 + tid;
    const int p = pos / 7, q = pos % 7;

    ull acc[8];
#pragma unroll
    for (int r = 0; r < 8; r++) acc[r] = 0ull;

    int off[9];
#pragma unroll
    for (int di = 0; di < 3; di++)
#pragma unroll
        for (int dj = 0; dj < 3; dj++)
            off[di * 3 + dj] = ((p + di) * 9 + (q + dj)) * PB;
    const ull* __restrict__ S2 = (const ull*)g_S2[cur];
#pragma unroll 2
    for (int o = 0; o < 64; o++) {
        const ull* base = S2 + o * 81 * PB + bp;
        const ull* wb = ws3 + o * 72;
#pragma unroll
        for (int t = 0; t < 9; t++) {
            ull sv = base[off[t]];
            const ull* wp = wb + t * 8;
#pragma unroll
            for (int r = 0; r < 8; r++) acc[r] = fma2(sv, wp[r], acc[r]);
        }
    }

    ull* __restrict__ outp = (ull*)g_S3[cur ^ 1];
    const int oidx = (c0 * 81 + (p + 1) * 9 + (q + 1)) * PB + bp;
#pragma unroll
    for (int r = 0; r < 8; r++) outp[oidx + r * (81 * PB)] = add2(acc[r], pk(b3[c0 + r]));
}

__global__ void __launch_bounds__(256) fwd4_kernel(int cur, const float* __restrict__ b4) {
    __shared__ ull ws[392 * 8];
    const int tid = threadIdx.x;
    const int j0 = blockIdx.y * 8;
    const int bp = blockIdx.x * 256 + tid;
    const ull* __restrict__ S3 = (const ull*)g_S3[cur];

    ull acc[8];
#pragma unroll
    for (int r = 0; r < 8; r++) acc[r] = 0ull;

    for (int ch = 0; ch < 8; ch++) {
        __syncthreads();
        for (int i = tid; i < 392; i += 256) {
            const float* src = &g_w4t[(ch * 392 + i) * 256 + j0];
            ull* dst = &ws[i * 8];
#pragma unroll
            for (int r = 0; r < 8; r++) dst[r] = pk(src[r]);
        }
        __syncthreads();
        for (int cc = 0; cc < 8; cc++) {
            const ull* cb = S3 + ((ch * 8 + cc) * 81) * PB + bp;
            const ull* wch = ws + cc * 392;
            int kk = 0;
#pragma unroll
            for (int pp = 1; pp <= 7; pp++) {
#pragma unroll
                for (int qq = 1; qq <= 7; qq++) {
                    ull sv = cb[(pp * 9 + qq) * PB];
                    const ull* wp = wch + kk * 8; kk++;
#pragma unroll
                    for (int r = 0; r < 8; r++) acc[r] = fma2(sv, wp[r], acc[r]);
                }
            }
        }
    }

    ull* __restrict__ outp = (ull*)g_S4[cur ^ 1];
#pragma unroll
    for (int r = 0; r < 8; r++) outp[(j0 + r) * PB + bp] = add2(acc[r], pk(b4[j0 + r]));
}

// ---------------- energy readout ----------------
__global__ void energy_zero(float* __restrict__ out) {
    int b = blockIdx.x * 256 + threadIdx.x;
    out[b] = 0.f;
}

__global__ void energy_partial(const float* __restrict__ vb, int fin,
                               float* __restrict__ out) {
    const int b = blockIdx.x * 256 + threadIdx.x;
    const int s = blockIdx.y;  // 0..7
    const float* __restrict__ S1 = g_S1[fin];
    const float* __restrict__ S2 = g_S2[fin];
    const float* __restrict__ S3 = g_S3[fin];
    const float* __restrict__ S4 = g_S4[fin];
    const float* __restrict__ F2 = g_S2[fin ^ 1];
    const float* __restrict__ F3 = g_S3[fin ^ 1];
    const float* __restrict__ F4 = g_S4[fin ^ 1];

    double e = 0.0;
    if (s == 0) {
        for (int p = 0; p < 784; p++) {
            float xv = g_XT[p * BB + b];
            float term = 0.5f * xv * xv - vb[p] * xv;
            e += (double)term;
        }
        for (int i = 0; i < 256; i++) {
            float sv = S4[i * BB + b];
            float term = 0.5f * sv * sv - sv * F4[i * BB + b];
            e += (double)term;
        }
    }
    for (int c = s * 4; c < s * 4 + 4; c++) {
        const float* Sr = S1 + c * 256 * BB;
        const float* Dr = g_D1 + c * 256 * BB;
        for (int pp = 1; pp <= 14; pp++)
            for (int vv = 1; vv <= 14; vv++) {
                int ro = (pp * 16 + vv) * BB + b;
                float sv = Sr[ro];
                float term = 0.5f * sv * sv - sv * Dr[ro];
                e += (double)term;
            }
    }
    if (s < 4) {
        for (int c = s * 16; c < s * 16 + 16; c++) {
            const float* Sr = S2 + c * 81 * BB;
            const float* Fr = F2 + c * 81 * BB;
            for (int pp = 1; pp <= 7; pp++)
                for (int qq = 1; qq <= 7; qq++) {
                    int ro = (pp * 9 + qq) * BB + b;
                    float sv = Sr[ro];
                    float term = 0.5f * sv * sv - sv * Fr[ro];
                    e += (double)term;
                }
        }
    } else {
        for (int c = (s - 4) * 16; c < (s - 4) * 16 + 16; c++) {
            const float* Sr = S3 + c * 81 * BB;
            const float* Fr = F3 + c * 81 * BB;
            for (int pp = 1; pp <= 7; pp++)
                for (int qq = 1; qq <= 7; qq++) {
                    int ro = (pp * 9 + qq) * BB + b;
                    float sv = Sr[ro];
                    float term = 0.5f * sv * sv - sv * Fr[ro];
                    e += (double)term;
                }
        }
    }
    atomicAdd(&out[b], (float)e);
}

// ---------------- launcher ----------------
extern "C" void kernel_launch(void* const* d_in, const int* in_sizes, int n_in,
                              void* d_out, int out_size) {
    const float* x  = (const float*)d_in[0];
    const float* vb = (const float*)d_in[1];
    const float* w1 = (const float*)d_in[2];
    const float* b1 = (const float*)d_in[3];
    const float* w2 = (const float*)d_in[4];
    const float* b2 = (const float*)d_in[5];
    const float* w3 = (const float*)d_in[6];
    const float* b3 = (const float*)d_in[7];
    const float* w4 = (const float*)d_in[8];
    const float* b4 = (const float*)d_in[9];
    float* out = (float*)d_out;

    cudaFuncSetAttribute(step_small, cudaFuncAttributeMaxDynamicSharedMemorySize, STEP_SMEM);

    zero_small<<<2048, 256>>>();
    basis_x<<<(784 * BBS + 255) / 256, 256>>>();
    transpose_x<<<dim3(25, 128), dim3(32, 8)>>>(x);
    prep_weights<<<1024, 256>>>(w2, w3, w4);
    compute_d1_small<<<dim3(BBS / 256, 196, 32), 256>>>(w1, b1);

    // 50-step relaxation on the 784 basis images + zero image (batch 1024).
    // 50 is even, so the final state lands back in buffer [0].
    int cs = 0;
    for (int t = 0; t < 50; t++) {
        step_small<<<800, 256, STEP_SMEM>>>(cs, b2, b3, b4);
        cs ^= 1;
    }

    // s50(x) = MM x + m0 : extract map, then expand to the full batch
    build_mm<<<(RTOT * 784 + 255) / 256, 256>>>();
    expand_kernel<<<(RTOT / 16) * 4, 256>>>();

    // epilogue: forward passes + energy at the expanded fixed point (fin = 0)
    compute_d1_big<<<dim3(BB / 256, 196, 32), 256>>>(w1, b1);
    fwd2_kernel<<<dim3(8, 49, 8), 256>>>(0, b2);
    fwd3_kernel<<<dim3(8, 49, 8), 256>>>(0, b3);
    fwd4_kernel<<<dim3(8, 32, 1), 256>>>(0, b4);

    energy_zero<<<16, 256>>>(out);
    energy_partial<<<dim3(16, 8), 256>>>(vb, 0, out);
}

// round 15
// speedup vs baseline: 3.8126x; 1.0657x over previous
#include <cuda_runtime.h>

#define BB 4096
#define PB 2048    // big-batch f32x2 pairs
#define BBS 800    // small (basis) batch: 784 basis + 1 zero + pad
#define PBS 400    // f32x2 pairs (rows are 3200 B, 16B-aligned)

// padded spatial layouts: S1 16x16 (14x14 interior), S2/S3 9x9 (7x7 interior)
constexpr int S1R = 32 * 256;   // 8192 rows
constexpr int S2R = 64 * 81;    // 5184 rows
constexpr int S4N = 256;
constexpr int RINT = 32 * 196 + 64 * 49 + 64 * 49 + 256;  // 12800 interior rows

typedef unsigned long long ull;

// ---------------- packed f32x2 helpers ----------------
__device__ __forceinline__ ull fma2(ull a, ull b, ull c) {
    ull d; asm("fma.rn.f32x2 %0, %1, %2, %3;" : "=l"(d) : "l"(a), "l"(b), "l"(c)); return d;
}
__device__ __forceinline__ ull add2(ull a, ull b) {
    ull d; asm("add.rn.f32x2 %0, %1, %2;" : "=l"(d) : "l"(a), "l"(b)); return d;
}
__device__ __forceinline__ ull mul2(ull a, ull b) {
    ull d; asm("mul.rn.f32x2 %0, %1, %2;" : "=l"(d) : "l"(a), "l"(b)); return d;
}
__device__ __forceinline__ ull pk(float x) {
    ull d; unsigned u = __float_as_uint(x);
    asm("mov.b64 %0, {%1, %1};" : "=l"(d) : "r"(u)); return d;
}
__device__ __forceinline__ ulonglong2 ld2(const ull* p) {
    return *reinterpret_cast<const ulonglong2*>(p);
}
__device__ __forceinline__ void st2(ull* p, ulonglong2 v) {
    *reinterpret_cast<ulonglong2*>(p) = v;
}

// ---------------- scratch (device globals; allocation-free) ----------------
// big-batch state (expand writes interior; halos stay at .bss zeros forever)
__device__ float g_S1[2][S1R * BB];
__device__ float g_S2[2][S2R * BB];
__device__ float g_S3[2][S2R * BB];
__device__ float g_S4[2][S4N * BB];
__device__ float g_D1[S1R * BB];        // conv1(x)+b1, big batch (energy only)
__device__ float g_XT[784 * BB];        // x transposed [pixel][batch]
// small (basis) relaxation state
__device__ float g_T1[2][S1R * BBS];
__device__ float g_T2[2][S2R * BBS];
__device__ float g_T3[2][S2R * BBS];
__device__ float g_T4[2][S4N * BBS];
__device__ float g_TD1[S1R * BBS];
__device__ float g_XTs[784 * BBS];
// linear map  s50(x) = MM·x + m0 (compact interior rows only)
__device__ float g_MM[RINT * 784];
__device__ float g_M0[RINT];
__device__ int   g_rowmap[RINT];        // compact row -> padded row index
// weight layouts
__device__ float g_w2a[64 * 9 * 32];    // [o][t][c]
__device__ float g_w2b[32 * 9 * 64];    // [c][t][o]
__device__ float g_w3a[64 * 9 * 64];    // [o][t][m]
__device__ float g_w3b[64 * 9 * 64];    // [m][t][o]
__device__ float g_w4t[3136 * 256];     // [k][j]
__device__ float g_w4r[49 * 256 * 64];  // [pos][j][c]

// ---------------- init / prep ----------------
__global__ void zero_small() {
    int stride = gridDim.x * blockDim.x;
    float4 z = make_float4(0.f, 0.f, 0.f, 0.f);
    const int n1 = S1R * BBS / 4;
    const int n2 = S2R * BBS / 4;
    const int n4 = S4N * BBS / 4;
    for (int i = blockIdx.x * blockDim.x + threadIdx.x; i < n1; i += stride) {
        reinterpret_cast<float4*>(g_T1[0])[i] = z;
        reinterpret_cast<float4*>(g_T1[1])[i] = z;
        reinterpret_cast<float4*>(g_TD1)[i] = z;
        if (i < n2) {
            reinterpret_cast<float4*>(g_T2[0])[i] = z;
            reinterpret_cast<float4*>(g_T2[1])[i] = z;
            reinterpret_cast<float4*>(g_T3[0])[i] = z;
            reinterpret_cast<float4*>(g_T3[1])[i] = z;
        }
        if (i < n4) {
            reinterpret_cast<float4*>(g_T4[0])[i] = z;
            reinterpret_cast<float4*>(g_T4[1])[i] = z;
        }
    }
}

__global__ void basis_x() {
    int idx = blockIdx.x * 256 + threadIdx.x;       // over 784*BBS
    if (idx >= 784 * BBS) return;
    int p = idx / BBS, c = idx % BBS;
    g_XTs[idx] = (c < 784 && p == c) ? 1.f : 0.f;
}

__global__ void build_rowmap() {
    int r = blockIdx.x * 256 + threadIdx.x;
    if (r >= RINT) return;
    int pr;
    if (r < 6272) {
        int c = r / 196, t = r % 196;
        pr = c * 256 + (t / 14 + 1) * 16 + (t % 14 + 1);
    } else if (r < 9408) {
        int r2 = r - 6272; int c = r2 / 49, t = r2 % 49;
        pr = S1R + c * 81 + (t / 7 + 1) * 9 + (t % 7 + 1);
    } else if (r < 12544) {
        int r2 = r - 9408; int c = r2 / 49, t = r2 % 49;
        pr = S1R + S2R + c * 81 + (t / 7 + 1) * 9 + (t % 7 + 1);
    } else {
        pr = S1R + 2 * S2R + (r - 12544);
    }
    g_rowmap[r] = pr;
}

__global__ void transpose_x(const float* __restrict__ x) {
    __shared__ float tile[32][33];
    int p0 = blockIdx.x * 32, b0 = blockIdx.y * 32;
    int tx = threadIdx.x, ty = threadIdx.y;
    for (int i = ty; i < 32; i += 8) {
        int p = p0 + tx;
        tile[i][tx] = (p < 784) ? x[(b0 + i) * 784 + p] : 0.f;
    }
    __syncthreads();
    for (int i = ty; i < 32; i += 8) {
        int p = p0 + i;
        if (p < 784) g_XT[p * BB + b0 + tx] = tile[tx][i];
    }
}

__global__ void prep_weights(const float* __restrict__ w2,
                             const float* __restrict__ w3,
                             const float* __restrict__ w4) {
    int stride = gridDim.x * blockDim.x;
    for (int idx = blockIdx.x * blockDim.x + threadIdx.x; idx < 802816; idx += stride) {
        if (idx < 18432) {  // w2: [o=64][c=32][t=9]
            int o = idx / 288, r = idx % 288, c = r / 9, t = r % 9;
            float v = w2[idx];
            g_w2a[(o * 9 + t) * 32 + c] = v;
            g_w2b[(c * 9 + t) * 64 + o] = v;
        }
        if (idx < 36864) {  // w3: [m=64][o=64][t=9]
            int m = idx / 576, r = idx % 576, o = r / 9, t = r % 9;
            float v = w3[idx];
            g_w3a[(o * 9 + t) * 64 + m] = v;
            g_w3b[(m * 9 + t) * 64 + o] = v;
        }
        {   // w4: [j=256][k=3136]
            int j = idx / 3136, k = idx % 3136;
            float v = w4[idx];
            g_w4t[k * 256 + j] = v;
            int c = k / 49, pos = k % 49;
            g_w4r[(pos * 256 + j) * 64 + c] = v;
        }
    }
}

// d1 = conv1(x)+b1 — small (basis) batch
__global__ void compute_d1_small(const float* __restrict__ w1, const float* __restrict__ b1) {
    int b = blockIdx.x * 256 + threadIdx.x;
    if (b >= BBS) return;
    int pos = blockIdx.y;
    int u = pos / 14, v = pos % 14;
    int c = blockIdx.z;
    float acc = b1[c];
#pragma unroll
    for (int di = 0; di < 3; di++) {
        int h = 2 * u + di - 1;
        if (h < 0 || h >= 28) continue;
#pragma unroll
        for (int dj = 0; dj < 3; dj++) {
            int w = 2 * v + dj - 1;
            if (w < 0 || w >= 28) continue;
            acc = fmaf(w1[c * 9 + di * 3 + dj], g_XTs[(h * 28 + w) * BBS + b], acc);
        }
    }
    g_TD1[(c * 256 + (u + 1) * 16 + (v + 1)) * BBS + b] = acc;
}

// d1 = conv1(x)+b1 — big batch (energy epilogue)
__global__ void compute_d1_big(const float* __restrict__ w1, const float* __restrict__ b1) {
    int b = blockIdx.x * 256 + threadIdx.x;
    int pos = blockIdx.y;
    int u = pos / 14, v = pos % 14;
    int c = blockIdx.z;
    float acc = b1[c];
#pragma unroll
    for (int di = 0; di < 3; di++) {
        int h = 2 * u + di - 1;
        if (h < 0 || h >= 28) continue;
#pragma unroll
        for (int dj = 0; dj < 3; dj++) {
            int w = 2 * v + dj - 1;
            if (w < 0 || w >= 28) continue;
            acc = fmaf(w1[c * 9 + di * 3 + dj], g_XT[(h * 28 + w) * BB + b], acc);
        }
    }
    g_D1[(c * 256 + (u + 1) * 16 + (v + 1)) * BB + b] = acc;
}

// ============================================================================
// Fused relaxation step on the BASIS batch (PBS=400 pairs).
// 16 output channels/block, 4 samples/thread; threads tid<200 compute,
// all 256 stage weights; __syncthreads never inside divergent regions.
// Grid = 800: [0,16): k4   [16,408): k1   [408,604): k2   [604,800): k3
// ============================================================================
#define STEP_SMEM 73728

#define ACC16(SV, WP) do {                                                     \
    _Pragma("unroll")                                                          \
    for (int _c = 0; _c < 16; _c++) {                                          \
        ull _w = (WP)[_c];                                                     \
        accA[_c] = fma2((SV).x, _w, accA[_c]);                                 \
        accB[_c] = fma2((SV).y, _w, accB[_c]);                                 \
    }                                                                          \
} while (0)

#define STAGE16D(DSTROW, SRCP) do {                                           \
    const float4* _s = reinterpret_cast<const float4*>(SRCP);                  \
    ull* _d = &wsu[(DSTROW) * 16];                                             \
    float4 _a = _s[0], _b = _s[1], _c = _s[2], _e = _s[3];                     \
    _d[0]  = pk(_a.x); _d[1]  = pk(_a.y); _d[2]  = pk(_a.z); _d[3]  = pk(_a.w);\
    _d[4]  = pk(_b.x); _d[5]  = pk(_b.y); _d[6]  = pk(_b.z); _d[7]  = pk(_b.w);\
    _d[8]  = pk(_c.x); _d[9]  = pk(_c.y); _d[10] = pk(_c.z); _d[11] = pk(_c.w);\
    _d[12] = pk(_e.x); _d[13] = pk(_e.y); _d[14] = pk(_e.z); _d[15] = pk(_e.w);\
} while (0)

__global__ void __launch_bounds__(256, 2) step_small(int cur,
                                                     const float* __restrict__ b2,
                                                     const float* __restrict__ b3,
                                                     const float* __restrict__ b4) {
    extern __shared__ ull wsu[];   // 576*16 ulls
    const int tid = threadIdx.x;
    const int bx = blockIdx.x;
    const ull half = pk(0.5f);
    const bool act = (tid < 200);

    const ull* __restrict__ S1c = (const ull*)g_T1[cur];
    ull* __restrict__ S1n = (ull*)g_T1[cur ^ 1];
    const ull* __restrict__ S2c = (const ull*)g_T2[cur];
    ull* __restrict__ S2n = (ull*)g_T2[cur ^ 1];
    const ull* __restrict__ S3c = (const ull*)g_T3[cur];
    ull* __restrict__ S3n = (ull*)g_T3[cur ^ 1];
    const ull* __restrict__ S4c = (const ull*)g_T4[cur];
    ull* __restrict__ S4n = (ull*)g_T4[cur ^ 1];
    const ull* __restrict__ D1p = (const ull*)g_TD1;

    ull accA[16], accB[16];
#pragma unroll
    for (int c = 0; c < 16; c++) { accA[c] = 0ull; accB[c] = 0ull; }

    if (bx < 16) {
        // ---------------- K4: s4' = 0.5*(s4 + W4 s3 + b4) ----------------
        const int j0 = bx * 16;
        const int u = 2 * tid;

        for (int ch = 0; ch < 8; ch++) {
            __syncthreads();
            for (int i = tid; i < 392; i += 256) STAGE16D(i, &g_w4t[(ch * 392 + i) * 256 + j0]);
            __syncthreads();
            if (act) {
                for (int cc = 0; cc < 8; cc++) {
                    const ull* cb = S3c + ((ch * 8 + cc) * 81) * PBS + u;
                    const ull* wch = wsu + cc * 49 * 16;
                    int kk = 0;
#pragma unroll
                    for (int pp = 1; pp <= 7; pp++) {
#pragma unroll
                        for (int qq = 1; qq <= 7; qq++) {
                            ulonglong2 sv = ld2(cb + (pp * 9 + qq) * PBS);
                            ACC16(sv, wch + kk * 16); kk++;
                        }
                    }
                }
            }
        }

        if (act) {
#pragma unroll
            for (int c = 0; c < 16; c++) {
                int ii = (j0 + c) * PBS + u;
                ull bias = pk(b4[j0 + c]);
                ulonglong2 si = ld2(S4c + ii);
                ulonglong2 o;
                o.x = mul2(add2(add2(si.x, accA[c]), bias), half);
                o.y = mul2(add2(add2(si.y, accB[c]), bias), half);
                st2(S4n + ii, o);
            }
        }
    } else if (bx < 408) {
        // ---------------- K1: s1' = 0.5*(s1 + d1 + tconv2(s2)) ----------------
        int t = bx - 16;
        const int pos = t % 196;
        const int c0 = (t / 196) * 16;
        const int u_ = 2 * tid;

        for (int i = tid; i < 576; i += 256) STAGE16D(i, &g_w2a[i * 32 + c0]);
        __syncthreads();
        if (!act) return;

        const int uu = pos / 14, vv = pos % 14;
        int p0r, p1r, wu0, wu1;
        if (uu & 1) { p0r = ((uu + 1) >> 1) + 1; wu0 = 0;
                      p1r = ((uu - 1) >> 1) + 1; wu1 = 2; }
        else        { p0r = (uu >> 1) + 1;       wu0 = 1;
                      p1r = 8;                   wu1 = 0; }
        int q0r, q1r, wv0, wv1;
        if (vv & 1) { q0r = ((vv + 1) >> 1) + 1; wv0 = 0;
                      q1r = ((vv - 1) >> 1) + 1; wv1 = 2; }
        else        { q0r = (vv >> 1) + 1;       wv0 = 1;
                      q1r = 8;                   wv1 = 0; }

        const int off00 = (p0r * 9 + q0r) * PBS, wr00 = wu0 * 3 + wv0;
        const int off01 = (p0r * 9 + q1r) * PBS, wr01 = wu0 * 3 + wv1;
        const int off10 = (p1r * 9 + q0r) * PBS, wr10 = wu1 * 3 + wv0;
        const int off11 = (p1r * 9 + q1r) * PBS, wr11 = wu1 * 3 + wv1;

#pragma unroll 1
        for (int o = 0; o < 64; o++) {
            const ull* base = S2c + o * 81 * PBS + u_;
            const ull* wb = wsu + (o * 9) * 16;
            { ulonglong2 sv = ld2(base + off00); ACC16(sv, wb + wr00 * 16); }
            { ulonglong2 sv = ld2(base + off01); ACC16(sv, wb + wr01 * 16); }
            { ulonglong2 sv = ld2(base + off10); ACC16(sv, wb + wr10 * 16); }
            { ulonglong2 sv = ld2(base + off11); ACC16(sv, wb + wr11 * 16); }
        }

        const int obase = (uu + 1) * 16 + (vv + 1);
#pragma unroll
        for (int c = 0; c < 16; c++) {
            int ii = ((c0 + c) * 256 + obase) * PBS + u_;
            ulonglong2 si = ld2(S1c + ii), d1 = ld2(D1p + ii);
            ulonglong2 o;
            o.x = mul2(add2(add2(si.x, d1.x), accA[c]), half);
            o.y = mul2(add2(add2(si.y, d1.y), accB[c]), half);
            st2(S1n + ii, o);
        }
    } else if (bx < 604) {
        // ---------------- K2: s2' = 0.5*(s2 + conv2(s1)+b2 + tconv3(s3)) ----------------
        int t = bx - 408;
        const int pos = t % 49;
        const int o0 = (t / 49) * 16;
        const int u_ = 2 * tid;
        const int p = pos / 7, q = pos % 7;

        for (int i = tid; i < 288; i += 256) STAGE16D(i, &g_w2b[i * 64 + o0]);
        for (int i = tid; i < 288; i += 256) STAGE16D(288 + i, &g_w3b[i * 64 + o0]);
        __syncthreads();

        int offc[9], offt[9];
#pragma unroll
        for (int di = 0; di < 3; di++)
#pragma unroll
            for (int dj = 0; dj < 3; dj++) {
                offc[di * 3 + dj] = ((2 * p + di) * 16 + (2 * q + dj)) * PBS;
                offt[di * 3 + dj] = ((p + 2 - di) * 9 + (q + 2 - dj)) * PBS;
            }

        if (act) {
            // conv2(s1): stride 2, branchless (padded 16x16)
#pragma unroll 1
            for (int c = 0; c < 32; c++) {
                const ull* base = S1c + c * 256 * PBS + u_;
                const ull* wb = wsu + (c * 9) * 16;
#pragma unroll
                for (int t2 = 0; t2 < 9; t2++) {
                    ulonglong2 sv = ld2(base + offc[t2]);
                    ACC16(sv, wb + t2 * 16);
                }
            }
            // tconv3(s3) m = 0..31
#pragma unroll 1
            for (int m = 0; m < 32; m++) {
                const ull* base = S3c + m * 81 * PBS + u_;
                const ull* wb = wsu + (288 + m * 9) * 16;
#pragma unroll
                for (int t2 = 0; t2 < 9; t2++) {
                    ulonglong2 sv = ld2(base + offt[t2]);
                    ACC16(sv, wb + t2 * 16);
                }
            }
        }
        __syncthreads();
        for (int i = tid; i < 288; i += 256) STAGE16D(i, &g_w3b[(288 + i) * 64 + o0]);
        __syncthreads();
        if (!act) return;
#pragma unroll 1
        for (int m = 32; m < 64; m++) {
            const ull* base = S3c + m * 81 * PBS + u_;
            const ull* wb = wsu + ((m - 32) * 9) * 16;
#pragma unroll
            for (int t2 = 0; t2 < 9; t2++) {
                ulonglong2 sv = ld2(base + offt[t2]);
                ACC16(sv, wb + t2 * 16);
            }
        }

        const int obase = (p + 1) * 9 + (q + 1);
#pragma unroll
        for (int c = 0; c < 16; c++) {
            int ii = ((o0 + c) * 81 + obase) * PBS + u_;
            ull bias = pk(b2[o0 + c]);
            ulonglong2 si = ld2(S2c + ii);
            ulonglong2 o;
            o.x = mul2(add2(add2(si.x, accA[c]), bias), half);
            o.y = mul2(add2(add2(si.y, accB[c]), bias), half);
            st2(S2n + ii, o);
        }
    } else {
        // ---------------- K3: s3' = 0.5*(s3 + conv3(s2)+b3 + W4^T s4) ----------------
        int t = bx - 604;
        const int pos = t % 49;
        const int c0 = (t / 49) * 16;
        const int u_ = 2 * tid;
        const int p = pos / 7, q = pos % 7;

        for (int i = tid; i < 576; i += 256) STAGE16D(i, &g_w3a[i * 64 + c0]);
        __syncthreads();

        if (act) {
            int off[9];
#pragma unroll
            for (int di = 0; di < 3; di++)
#pragma unroll
                for (int dj = 0; dj < 3; dj++)
                    off[di * 3 + dj] = ((p + di) * 9 + (q + dj)) * PBS;
#pragma unroll 1
            for (int o = 0; o < 64; o++) {
                const ull* base = S2c + o * 81 * PBS + u_;
                const ull* wb = wsu + (o * 9) * 16;
#pragma unroll
                for (int t2 = 0; t2 < 9; t2++) {
                    ulonglong2 sv = ld2(base + off[t2]);
                    ACC16(sv, wb + t2 * 16);
                }
            }
        }
        __syncthreads();
        for (int j = tid; j < 256; j += 256) STAGE16D(j, &g_w4r[(pos * 256 + j) * 64 + c0]);
        __syncthreads();
        if (!act) return;
#pragma unroll 1
        for (int j = 0; j < 256; j++) {
            ulonglong2 sv = ld2(S4c + j * PBS + u_);
            ACC16(sv, wsu + j * 16);
        }

        const int obase = (p + 1) * 9 + (q + 1);
#pragma unroll
        for (int c = 0; c < 16; c++) {
            int ii = ((c0 + c) * 81 + obase) * PBS + u_;
            ull bias = pk(b3[c0 + c]);
            ulonglong2 si = ld2(S3c + ii);
            ulonglong2 o;
            o.x = mul2(add2(add2(si.x, accA[c]), bias), half);
            o.y = mul2(add2(add2(si.y, accB[c]), bias), half);
            st2(S3n + ii, o);
        }
    }
}

// ---------------- MM / m0 extraction (final state in buffer [0]) ------------
__device__ __forceinline__ float small_read(int pr, int c) {
    if (pr < S1R) return g_T1[0][pr * BBS + c];
    if (pr < S1R + S2R) return g_T2[0][(pr - S1R) * BBS + c];
    if (pr < S1R + 2 * S2R) return g_T3[0][(pr - S1R - S2R) * BBS + c];
    return g_T4[0][(pr - S1R - 2 * S2R) * BBS + c];
}

__global__ void build_mm() {
    int idx = blockIdx.x * 256 + threadIdx.x;   // over RINT*784
    if (idx >= RINT * 784) return;
    int r = idx / 784, i = idx % 784;
    int pr = g_rowmap[r];
    float m0 = small_read(pr, 784);
    g_MM[idx] = small_read(pr, i) - m0;
    if (i == 0) g_M0[r] = m0;
}

// ---------------- expand GEMM: interior rows only ----------------
// grid: (RINT/16) row-blocks x 4 batch-slices; 16 compact rows x 1024 samples
__global__ void __launch_bounds__(256) expand_kernel() {
    __shared__ ull smw[196 * 16];    // 25088 B (k-major, 16 rows per k)
    __shared__ float m0s[16];
    __shared__ int rmap[16];
    const int tid = threadIdx.x;
    const int bx = blockIdx.x;
    const int bslice = bx & 3;
    const int row0 = (bx >> 2) * 16;
    const int u = bslice * 512 + 2 * tid;

    if (tid < 16) { m0s[tid] = g_M0[row0 + tid]; rmap[tid] = g_rowmap[row0 + tid]; }
    __syncthreads();

    ull accA[16], accB[16];
#pragma unroll
    for (int c = 0; c < 16; c++) { accA[c] = pk(m0s[c]); accB[c] = accA[c]; }

    const ull* __restrict__ XT2 = (const ull*)g_XT;
    for (int ch = 0; ch < 4; ch++) {
        __syncthreads();
        for (int idx = tid; idx < 16 * 196; idx += 256) {
            int r = idx / 196, k = idx % 196;
            smw[k * 16 + r] = pk(g_MM[(row0 + r) * 784 + ch * 196 + k]);
        }
        __syncthreads();
#pragma unroll 1
        for (int k = 0; k < 196; k++) {
            ulonglong2 sv = ld2(XT2 + (ch * 196 + k) * PB + u);
            const ull* wp = &smw[k * 16];
            ACC16(sv, wp);
        }
    }

#pragma unroll
    for (int c = 0; c < 16; c++) {
        int pr = rmap[c];
        ull* dst;
        if (pr < S1R)                { dst = (ull*)g_S1[0] + pr * PB; }
        else if (pr < S1R + S2R)     { dst = (ull*)g_S2[0] + (pr - S1R) * PB; }
        else if (pr < S1R + 2 * S2R) { dst = (ull*)g_S3[0] + (pr - S1R - S2R) * PB; }
        else                         { dst = (ull*)g_S4[0] + (pr - S1R - 2 * S2R) * PB; }
        ulonglong2 o; o.x = accA[c]; o.y = accB[c];
        st2(dst + u, o);
    }
}

// ============================================================================
// Forward-only kernels for energy readout (big batch) — proven versions
// ============================================================================
__global__ void __launch_bounds__(256) fwd2_kernel(int cur, const float* __restrict__ b2) {
    __shared__ float ws2[288 * 8];
    const int tid = threadIdx.x;
    const int o0 = blockIdx.z * 8;
    for (int i = tid; i < 288; i += 256) {
        const float* src = &g_w2b[i * 64 + o0];
        float* dst = &ws2[i * 8];
#pragma unroll
        for (int r = 0; r < 8; r++) dst[r] = src[r];
    }
    __syncthreads();

    const int bp = blockIdx.x * 256 + tid;
    const int pos = blockIdx.y;
    const int p = pos / 7, q = pos % 7;

    ull acc[8];
#pragma unroll
    for (int r = 0; r < 8; r++) acc[r] = 0ull;

    int off[9];
#pragma unroll
    for (int di = 0; di < 3; di++)
#pragma unroll
        for (int dj = 0; dj < 3; dj++)
            off[di * 3 + dj] = ((2 * p + di) * 16 + (2 * q + dj)) * PB;
    const ull* __restrict__ S1 = (const ull*)g_S1[cur];
#pragma unroll 2
    for (int c = 0; c < 32; c++) {
        const ull* base = S1 + c * 256 * PB + bp;
        const float* wb = ws2 + c * 72;
#pragma unroll
        for (int t = 0; t < 9; t++) {
            ull sv = base[off[t]];
            const float* wp = wb + t * 8;
#pragma unroll
            for (int r = 0; r < 8; r++) acc[r] = fma2(sv, pk(wp[r]), acc[r]);
        }
    }

    ull* __restrict__ outp = (ull*)g_S2[cur ^ 1];
    const int oidx = (o0 * 81 + (p + 1) * 9 + (q + 1)) * PB + bp;
#pragma unroll
    for (int r = 0; r < 8; r++) outp[oidx + r * (81 * PB)] = add2(acc[r], pk(b2[o0 + r]));
}

__global__ void __launch_bounds__(256) fwd3_kernel(int cur, const float* __restrict__ b3) {
    __shared__ ull ws3[576 * 8];
    const int tid = threadIdx.x;
    const int c0 = blockIdx.z * 8;
    const int pos = blockIdx.y;
    for (int i = tid; i < 576; i += 256) {
        const float* src = &g_w3a[i * 64 + c0];
        ull* dst = &ws3[i * 8];
#pragma unroll
        for (int r = 0; r < 8; r++) dst[r] = pk(src[r]);
    }
    __syncthreads();

    const int bp = blockIdx.x * 256 + tid;
    const int p = pos / 7, q = pos % 7;

    ull acc[8];
#pragma unroll
    for (int r = 0; r < 8; r++) acc[r] = 0ull;

    int off[9];
#pragma unroll
    for (int di = 0; di < 3; di++)
#pragma unroll
        for (int dj = 0; dj < 3; dj++)
            off[di * 3 + dj] = ((p + di) * 9 + (q + dj)) * PB;
    const ull* __restrict__ S2 = (const ull*)g_S2[cur];
#pragma unroll 2
    for (int o = 0; o < 64; o++) {
        const ull* base = S2 + o * 81 * PB + bp;
        const ull* wb = ws3 + o * 72;
#pragma unroll
        for (int t = 0; t < 9; t++) {
            ull sv = base[off[t]];
            const ull* wp = wb + t * 8;
#pragma unroll
            for (int r = 0; r < 8; r++) acc[r] = fma2(sv, wp[r], acc[r]);
        }
    }

    ull* __restrict__ outp = (ull*)g_S3[cur ^ 1];
    const int oidx = (c0 * 81 + (p + 1) * 9 + (q + 1)) * PB + bp;
#pragma unroll
    for (int r = 0; r < 8; r++) outp[oidx + r * (81 * PB)] = add2(acc[r], pk(b3[c0 + r]));
}

__global__ void __launch_bounds__(256) fwd4_kernel(int cur, const float* __restrict__ b4) {
    __shared__ ull ws[392 * 8];
    const int tid = threadIdx.x;
    const int j0 = blockIdx.y * 8;
    const int bp = blockIdx.x * 256 + tid;
    const ull* __restrict__ S3 = (const ull*)g_S3[cur];

    ull acc[8];
#pragma unroll
    for (int r = 0; r < 8; r++) acc[r] = 0ull;

    for (int ch = 0; ch < 8; ch++) {
        __syncthreads();
        for (int i = tid; i < 392; i += 256) {
            const float* src = &g_w4t[(ch * 392 + i) * 256 + j0];
            ull* dst = &ws[i * 8];
#pragma unroll
            for (int r = 0; r < 8; r++) dst[r] = pk(src[r]);
        }
        __syncthreads();
        for (int cc = 0; cc < 8; cc++) {
            const ull* cb = S3 + ((ch * 8 + cc) * 81) * PB + bp;
            const ull* wch = ws + cc * 392;
            int kk = 0;
#pragma unroll
            for (int pp = 1; pp <= 7; pp++) {
#pragma unroll
                for (int qq = 1; qq <= 7; qq++) {
                    ull sv = cb[(pp * 9 + qq) * PB];
                    const ull* wp = wch + kk * 8; kk++;
#pragma unroll
                    for (int r = 0; r < 8; r++) acc[r] = fma2(sv, wp[r], acc[r]);
                }
            }
        }
    }

    ull* __restrict__ outp = (ull*)g_S4[cur ^ 1];
#pragma unroll
    for (int r = 0; r < 8; r++) outp[(j0 + r) * PB + bp] = add2(acc[r], pk(b4[j0 + r]));
}

// ---------------- energy readout ----------------
__global__ void energy_zero(float* __restrict__ out) {
    int b = blockIdx.x * 256 + threadIdx.x;
    out[b] = 0.f;
}

__global__ void energy_partial(const float* __restrict__ vb, int fin,
                               float* __restrict__ out) {
    const int b = blockIdx.x * 256 + threadIdx.x;
    const int s = blockIdx.y;  // 0..7
    const float* __restrict__ S1 = g_S1[fin];
    const float* __restrict__ S2 = g_S2[fin];
    const float* __restrict__ S3 = g_S3[fin];
    const float* __restrict__ S4 = g_S4[fin];
    const float* __restrict__ F2 = g_S2[fin ^ 1];
    const float* __restrict__ F3 = g_S3[fin ^ 1];
    const float* __restrict__ F4 = g_S4[fin ^ 1];

    double e = 0.0;
    if (s == 0) {
        for (int p = 0; p < 784; p++) {
            float xv = g_XT[p * BB + b];
            float term = 0.5f * xv * xv - vb[p] * xv;
            e += (double)term;
        }
        for (int i = 0; i < 256; i++) {
            float sv = S4[i * BB + b];
            float term = 0.5f * sv * sv - sv * F4[i * BB + b];
            e += (double)term;
        }
    }
    for (int c = s * 4; c < s * 4 + 4; c++) {
        const float* Sr = S1 + c * 256 * BB;
        const float* Dr = g_D1 + c * 256 * BB;
        for (int pp = 1; pp <= 14; pp++)
            for (int vv = 1; vv <= 14; vv++) {
                int ro = (pp * 16 + vv) * BB + b;
                float sv = Sr[ro];
                float term = 0.5f * sv * sv - sv * Dr[ro];
                e += (double)term;
            }
    }
    if (s < 4) {
        for (int c = s * 16; c < s * 16 + 16; c++) {
            const float* Sr = S2 + c * 81 * BB;
            const float* Fr = F2 + c * 81 * BB;
            for (int pp = 1; pp <= 7; pp++)
                for (int qq = 1; qq <= 7; qq++) {
                    int ro = (pp * 9 + qq) * BB + b;
                    float sv = Sr[ro];
                    float term = 0.5f * sv * sv - sv * Fr[ro];
                    e += (double)term;
                }
        }
    } else {
        for (int c = (s - 4) * 16; c < (s - 4) * 16 + 16; c++) {
            const float* Sr = S3 + c * 81 * BB;
            const float* Fr = F3 + c * 81 * BB;
            for (int pp = 1; pp <= 7; pp++)
                for (int qq = 1; qq <= 7; qq++) {
                    int ro = (pp * 9 + qq) * BB + b;
                    float sv = Sr[ro];
                    float term = 0.5f * sv * sv - sv * Fr[ro];
                    e += (double)term;
                }
        }
    }
    atomicAdd(&out[b], (float)e);
}

// ---------------- launcher ----------------
extern "C" void kernel_launch(void* const* d_in, const int* in_sizes, int n_in,
                              void* d_out, int out_size) {
    const float* x  = (const float*)d_in[0];
    const float* vb = (const float*)d_in[1];
    const float* w1 = (const float*)d_in[2];
    const float* b1 = (const float*)d_in[3];
    const float* w2 = (const float*)d_in[4];
    const float* b2 = (const float*)d_in[5];
    const float* w3 = (const float*)d_in[6];
    const float* b3 = (const float*)d_in[7];
    const float* w4 = (const float*)d_in[8];
    const float* b4 = (const float*)d_in[9];
    float* out = (float*)d_out;

    cudaFuncSetAttribute(step_small, cudaFuncAttributeMaxDynamicSharedMemorySize, STEP_SMEM);

    zero_small<<<2048, 256>>>();
    basis_x<<<(784 * BBS + 255) / 256, 256>>>();
    build_rowmap<<<(RINT + 255) / 256, 256>>>();
    transpose_x<<<dim3(25, 128), dim3(32, 8)>>>(x);
    prep_weights<<<1024, 256>>>(w2, w3, w4);
    compute_d1_small<<<dim3((BBS + 255) / 256, 196, 32), 256>>>(w1, b1);

    // 50-step relaxation on the 784 basis images + zero image (batch 800).
    // 50 is even, so the final state lands back in buffer [0].
    int cs = 0;
    for (int t = 0; t < 50; t++) {
        step_small<<<800, 256, STEP_SMEM>>>(cs, b2, b3, b4);
        cs ^= 1;
    }

    // s50(x) = MM x + m0 : extract compact map, then expand interior rows
    build_mm<<<(RINT * 784 + 255) / 256, 256>>>();
    expand_kernel<<<(RINT / 16) * 4, 256>>>();

    // epilogue: forward passes + energy at the expanded fixed point (fin = 0)
    compute_d1_big<<<dim3(BB / 256, 196, 32), 256>>>(w1, b1);
    fwd2_kernel<<<dim3(8, 49, 8), 256>>>(0, b2);
    fwd3_kernel<<<dim3(8, 49, 8), 256>>>(0, b3);
    fwd4_kernel<<<dim3(8, 32, 1), 256>>>(0, b4);

    energy_zero<<<16, 256>>>(out);
    energy_partial<<<dim3(16, 8), 256>>>(vb, 0, out);
}